// round 1
// baseline (speedup 1.0000x reference)
#include <cuda_runtime.h>
#include <math.h>

#define BB 2
#define EE 1024
#define SS 2048
#define HH 16
#define DD 1024
#define DH 64

// ---- scratch (static __device__ arrays; no allocations allowed) ----
__device__ float g_QP[(size_t)BB * DD * SS];
__device__ float g_KP[(size_t)BB * DD * SS];
__device__ float g_VP[(size_t)BB * DD * SS];
__device__ float g_SC[(size_t)BB * HH * SS * SS];  // scores, softmaxed in place
__device__ float g_AT[(size_t)BB * DD * SS];

// ============================================================================
// Generic NN SGEMM: C[m,n] = sum_k A[m,k]*B[k,n] (+bias[m]); batch via z.
// CAUSAL: clamp K loop to the end of this column block (attn = V @ P).
// ============================================================================
template <int BM, int BN, int BK, int TM, int TN, bool CAUSAL>
__global__ void gemm_nn(const float* __restrict__ A, const float* __restrict__ Bmat,
                        const float* __restrict__ bias, float* __restrict__ C,
                        int K, int lda, int ldb, int ldc,
                        size_t sA, size_t sB, size_t sC)
{
    constexpr int THREADS = (BM / TM) * (BN / TN);
    const int z = blockIdx.z;
    A    += (size_t)z * sA;
    Bmat += (size_t)z * sB;
    C    += (size_t)z * sC;

    const int n0 = blockIdx.x * BN;
    const int m0 = blockIdx.y * BM;
    int Kend = K;
    if (CAUSAL) Kend = min(K, n0 + BN);

    __shared__ __align__(16) float As[BK][BM + 4];
    __shared__ __align__(16) float Bs[BK][BN];

    const int tid = threadIdx.x;
    const int tc  = tid % (BN / TN);
    const int tr  = tid / (BN / TN);

    float acc[TM][TN] = {};

    for (int k0 = 0; k0 < Kend; k0 += BK) {
        // A tile (BM x BK), row-major lda; store transposed into As
        constexpr int AV = BM * BK / 4;
        #pragma unroll
        for (int v = tid; v < AV; v += THREADS) {
            int row = v / (BK / 4);
            int c4  = (v % (BK / 4)) * 4;
            float4 t = *reinterpret_cast<const float4*>(&A[(size_t)(m0 + row) * lda + k0 + c4]);
            As[c4 + 0][row] = t.x; As[c4 + 1][row] = t.y;
            As[c4 + 2][row] = t.z; As[c4 + 3][row] = t.w;
        }
        // B tile (BK x BN), row-major ldb
        constexpr int BV = BK * BN / 4;
        #pragma unroll
        for (int v = tid; v < BV; v += THREADS) {
            int row = v / (BN / 4);
            int c4  = (v % (BN / 4)) * 4;
            *reinterpret_cast<float4*>(&Bs[row][c4]) =
                *reinterpret_cast<const float4*>(&Bmat[(size_t)(k0 + row) * ldb + n0 + c4]);
        }
        __syncthreads();
        #pragma unroll
        for (int kk = 0; kk < BK; ++kk) {
            float ra[TM], rb[TN];
            #pragma unroll
            for (int i = 0; i < TM; i += 4)
                *reinterpret_cast<float4*>(&ra[i]) =
                    *reinterpret_cast<const float4*>(&As[kk][tr * TM + i]);
            #pragma unroll
            for (int j = 0; j < TN; j += 4)
                *reinterpret_cast<float4*>(&rb[j]) =
                    *reinterpret_cast<const float4*>(&Bs[kk][tc * TN + j]);
            #pragma unroll
            for (int i = 0; i < TM; ++i)
                #pragma unroll
                for (int j = 0; j < TN; ++j)
                    acc[i][j] = fmaf(ra[i], rb[j], acc[i][j]);
        }
        __syncthreads();
    }

    #pragma unroll
    for (int i = 0; i < TM; ++i) {
        int m = m0 + tr * TM + i;
        float bv = bias ? bias[m] : 0.f;
        #pragma unroll
        for (int j = 0; j < TN; j += 4) {
            float4 t;
            t.x = acc[i][j + 0] + bv;
            t.y = acc[i][j + 1] + bv;
            t.z = acc[i][j + 2] + bv;
            t.w = acc[i][j + 3] + bv;
            *reinterpret_cast<float4*>(&C[(size_t)m * ldc + n0 + tc * TN + j]) = t;
        }
    }
}

// ============================================================================
// TN GEMM for scores: C[m,n] = scale * sum_c A[c,m]*B[c,n]; skips blocks
// fully above the causal diagonal (m = key index, n = query index).
// ============================================================================
template <int BM, int BN, int BK, int TM, int TN>
__global__ void gemm_tn_scores(const float* __restrict__ A, const float* __restrict__ Bmat,
                               float* __restrict__ C, int Kd,
                               int lda, int ldb, int ldc,
                               size_t sA, size_t sB, size_t sC, float scale)
{
    constexpr int THREADS = (BM / TM) * (BN / TN);
    const int n0 = blockIdx.x * BN;
    const int m0 = blockIdx.y * BM;
    if (m0 > n0 + BN - 1) return;  // whole block causally masked (k > q)

    const int z = blockIdx.z;
    A    += (size_t)z * sA;
    Bmat += (size_t)z * sB;
    C    += (size_t)z * sC;

    __shared__ __align__(16) float As[BK][BM + 4];
    __shared__ __align__(16) float Bs[BK][BN];

    const int tid = threadIdx.x;
    const int tc  = tid % (BN / TN);
    const int tr  = tid / (BN / TN);

    float acc[TM][TN] = {};

    for (int k0 = 0; k0 < Kd; k0 += BK) {
        constexpr int AV = BK * BM / 4;
        #pragma unroll
        for (int v = tid; v < AV; v += THREADS) {
            int row = v / (BM / 4);
            int c4  = (v % (BM / 4)) * 4;
            *reinterpret_cast<float4*>(&As[row][c4]) =
                *reinterpret_cast<const float4*>(&A[(size_t)(k0 + row) * lda + m0 + c4]);
        }
        constexpr int BV = BK * BN / 4;
        #pragma unroll
        for (int v = tid; v < BV; v += THREADS) {
            int row = v / (BN / 4);
            int c4  = (v % (BN / 4)) * 4;
            *reinterpret_cast<float4*>(&Bs[row][c4]) =
                *reinterpret_cast<const float4*>(&Bmat[(size_t)(k0 + row) * ldb + n0 + c4]);
        }
        __syncthreads();
        #pragma unroll
        for (int kk = 0; kk < BK; ++kk) {
            float ra[TM], rb[TN];
            #pragma unroll
            for (int i = 0; i < TM; i += 4)
                *reinterpret_cast<float4*>(&ra[i]) =
                    *reinterpret_cast<const float4*>(&As[kk][tr * TM + i]);
            #pragma unroll
            for (int j = 0; j < TN; j += 4)
                *reinterpret_cast<float4*>(&rb[j]) =
                    *reinterpret_cast<const float4*>(&Bs[kk][tc * TN + j]);
            #pragma unroll
            for (int i = 0; i < TM; ++i)
                #pragma unroll
                for (int j = 0; j < TN; ++j)
                    acc[i][j] = fmaf(ra[i], rb[j], acc[i][j]);
        }
        __syncthreads();
    }

    #pragma unroll
    for (int i = 0; i < TM; ++i) {
        int m = m0 + tr * TM + i;
        #pragma unroll
        for (int j = 0; j < TN; j += 4) {
            float4 t;
            t.x = acc[i][j + 0] * scale;
            t.y = acc[i][j + 1] * scale;
            t.z = acc[i][j + 2] * scale;
            t.w = acc[i][j + 3] * scale;
            *reinterpret_cast<float4*>(&C[(size_t)m * ldc + n0 + tc * TN + j]) = t;
        }
    }
}

// ============================================================================
// In-place causal column softmax over k (row index). One thread per query q.
// Adds qk_mask[b,k,0,q] and k_mask[b,k] in the live region; zero-fills up to
// the next 128-aligned row so the causal attn GEMM reads clean tiles.
// ============================================================================
__global__ void softmax_causal(float* __restrict__ SC, const float* __restrict__ qk_mask,
                               const float* __restrict__ k_mask)
{
    const int z = blockIdx.y;      // b*H + h
    const int b = z / HH;
    const int q = blockIdx.x * blockDim.x + threadIdx.x;

    float* col        = SC + (size_t)z * SS * SS + q;
    const float* qm   = qk_mask + (size_t)b * SS * SS + q;  // [b, k, 0, q]
    const float* km   = k_mask + (size_t)b * SS;            // [b, k]

    float m = -1e30f, l = 0.f;
    for (int k = 0; k <= q; ++k) {
        float s  = col[(size_t)k * SS] + qm[(size_t)k * SS] + km[k];
        float mn = fmaxf(m, s);
        l = l * __expf(m - mn) + __expf(s - mn);
        m = mn;
    }
    const float inv = 1.f / l;
    for (int k = 0; k <= q; ++k) {
        float s = col[(size_t)k * SS] + qm[(size_t)k * SS] + km[k];
        col[(size_t)k * SS] = __expf(s - m) * inv;
    }
    const int kend = ((q >> 7) + 1) << 7;
    for (int k = q + 1; k < kend; ++k) col[(size_t)k * SS] = 0.f;
}

// ============================================================================
extern "C" void kernel_launch(void* const* d_in, const int* in_sizes, int n_in,
                              void* d_out, int out_size)
{
    (void)in_sizes; (void)n_in; (void)out_size;
    const float* q       = (const float*)d_in[0];
    const float* k       = (const float*)d_in[1];
    const float* v       = (const float*)d_in[2];
    const float* qk_mask = (const float*)d_in[3];
    const float* k_mask  = (const float*)d_in[4];
    const float* Wq = (const float*)d_in[5];
    const float* bq = (const float*)d_in[6];
    const float* Wk = (const float*)d_in[7];
    const float* bk = (const float*)d_in[8];
    const float* Wv = (const float*)d_in[9];
    const float* bv = (const float*)d_in[10];
    const float* Wo = (const float*)d_in[11];
    const float* bo = (const float*)d_in[12];
    float* out = (float*)d_out;

    float *QP, *KP, *VP, *SC, *AT;
    cudaGetSymbolAddress((void**)&QP, g_QP);
    cudaGetSymbolAddress((void**)&KP, g_KP);
    cudaGetSymbolAddress((void**)&VP, g_VP);
    cudaGetSymbolAddress((void**)&SC, g_SC);
    cudaGetSymbolAddress((void**)&AT, g_AT);

    const size_t sX = (size_t)EE * SS;   // per-batch input stride
    const size_t sP = (size_t)DD * SS;   // per-batch projection stride
    const size_t sH = (size_t)DH * SS;   // per-(b,h) head stride (D = H*DH)
    const size_t sS = (size_t)SS * SS;   // per-(b,h) score stride

    // 1) projections: QP/KP/VP[b, o, s] = W @ x_b + bias
    dim3 gp(SS / 128, DD / 128, BB);
    gemm_nn<128, 128, 16, 8, 8, false><<<gp, 256>>>(Wq, q, bq, QP, EE, EE, SS, SS, 0, sX, sP);
    gemm_nn<128, 128, 16, 8, 8, false><<<gp, 256>>>(Wk, k, bk, KP, EE, EE, SS, SS, 0, sX, sP);
    gemm_nn<128, 128, 16, 8, 8, false><<<gp, 256>>>(Wv, v, bv, VP, EE, EE, SS, SS, 0, sX, sP);

    // 2) scores[z, kk, qq] = 1/8 * sum_c K[c,kk] * Q[c,qq]   (causal blocks only)
    dim3 gs(SS / 128, SS / 128, BB * HH);
    gemm_tn_scores<128, 128, 16, 8, 8><<<gs, 256>>>(KP, QP, SC, DH, SS, SS, SS,
                                                    sH, sH, sS, 0.125f);

    // 3) causal softmax over k, in place (adds qk_mask + k_mask)
    softmax_causal<<<dim3(SS / 256, BB * HH), 256>>>(SC, qk_mask, k_mask);

    // 4) attn[z, c, qq] = sum_k V[c,k] * P[k,qq]   (K clamped causally)
    dim3 ga(SS / 128, 1, BB * HH);
    gemm_nn<64, 128, 16, 4, 8, true><<<ga, 256>>>(VP, SC, nullptr, AT, SS, SS, SS, SS,
                                                  sH, sS, sH);

    // 5) output projection
    dim3 go(SS / 128, DD / 128, BB);
    gemm_nn<128, 128, 16, 8, 8, false><<<go, 256>>>(Wo, AT, bo, out, DD, DD, SS, SS,
                                                    0, sP, sP);
}

// round 2
// speedup vs baseline: 1.6918x; 1.6918x over previous
#include <cuda_runtime.h>
#include <stdint.h>
#include <math.h>

#define BB 2
#define EE 1024
#define SS 2048
#define HH 16
#define DD 1024
#define DH 64

// ---- scratch (static __device__ arrays; no allocations allowed) ----
__device__ float g_QP[(size_t)BB * DD * SS];
__device__ float g_KP[(size_t)BB * DD * SS];
__device__ float g_VP[(size_t)BB * DD * SS];
__device__ float g_SC[(size_t)BB * HH * SS * SS];  // scores, softmaxed in place
__device__ float g_AT[(size_t)BB * DD * SS];

__device__ __forceinline__ uint32_t f2tf(float x) {
    uint32_t u;
    asm("cvt.rna.tf32.f32 %0, %1;" : "=r"(u) : "f"(x));
    return u;
}

__device__ __forceinline__ void mma_tf32(float* c, const uint32_t* a, const uint32_t* b) {
    asm volatile(
        "mma.sync.aligned.m16n8k8.row.col.f32.tf32.tf32.f32 "
        "{%0,%1,%2,%3}, {%4,%5,%6,%7}, {%8,%9}, {%0,%1,%2,%3};"
        : "+f"(c[0]), "+f"(c[1]), "+f"(c[2]), "+f"(c[3])
        : "r"(a[0]), "r"(a[1]), "r"(a[2]), "r"(a[3]), "r"(b[0]), "r"(b[1]));
}

// ============================================================================
// tf32 tensor-core block GEMM.
//   C[m,n] = scale * sum_k A[.,.]*B[k,n] (+ bias[m])
//   TRANS_A=false: A is MxK row-major (lda = K stride)
//   TRANS_A=true : A is KxM row-major (lda = M stride)  [scores: K^T @ Q]
//   CSKIP : skip blocks fully above causal diagonal (m=key, n=query)
//   CCLAMP: clamp K loop to n0+BN (attn = V @ P, P causal lower-triangular)
// Block: BM x BN x 16, 8 warps (WM x WN), warp tile (BM/WM) x (BN/WN),
// mma m16n8k8.
// ============================================================================
template <int BM, int BN, int WM, int WN, bool TRANS_A, bool CSKIP, bool CCLAMP>
__global__ void __launch_bounds__(WM * WN * 32, 2)
mma_gemm(const float* __restrict__ A, const float* __restrict__ Bmat,
         const float* __restrict__ bias, float* __restrict__ C,
         int K, int lda, int ldb, int ldc,
         size_t sA, size_t sB, size_t sC, float scale)
{
    constexpr int BK = 16;
    constexpr int THREADS = WM * WN * 32;
    constexpr int MT = BM / WM / 16;   // m16 tiles per warp
    constexpr int NT = BN / WN / 8;    // n8 tiles per warp
    constexpr int ASTRIDE = TRANS_A ? (BM + 8) : 20;  // k-major : m-major(pad 20)
    constexpr int BSTRIDE = BN + 8;

    const int n0 = blockIdx.x * BN;
    const int m0 = blockIdx.y * BM;
    if (CSKIP && m0 > n0 + BN - 1) return;

    const int z = blockIdx.z;
    A    += (size_t)z * sA;
    Bmat += (size_t)z * sB;
    C    += (size_t)z * sC;

    int Kend = K;
    if (CCLAMP) Kend = min(K, n0 + BN);

    __shared__ __align__(16) uint32_t As[TRANS_A ? (BK * ASTRIDE) : (BM * ASTRIDE)];
    __shared__ __align__(16) uint32_t Bs[BK * BSTRIDE];

    const int tid  = threadIdx.x;
    const int lane = tid & 31;
    const int wid  = tid >> 5;
    const int g    = lane >> 2;   // group id (0..7)
    const int t    = lane & 3;    // thread-in-group (0..3)
    const int wm   = (wid / WN) * (BM / WM);
    const int wn   = (wid % WN) * (BN / WN);

    float acc[MT][NT][4] = {};

    for (int k0 = 0; k0 < Kend; k0 += BK) {
        // ---- load A tile ----
        if (TRANS_A) {
            // global A[k][m]; coalesced float4 along m; smem k-major
            constexpr int AV = BK * (BM / 4);
            #pragma unroll
            for (int v = tid; v < AV; v += THREADS) {
                int kr = v / (BM / 4);
                int c4 = (v % (BM / 4)) * 4;
                float4 f = *reinterpret_cast<const float4*>(
                    &A[(size_t)(k0 + kr) * lda + m0 + c4]);
                uint4 u = {f2tf(f.x), f2tf(f.y), f2tf(f.z), f2tf(f.w)};
                *reinterpret_cast<uint4*>(&As[kr * ASTRIDE + c4]) = u;
            }
        } else {
            // global A[m][k]; coalesced float4 along k; smem m-major (stride 20)
            constexpr int AV = BM * (BK / 4);
            #pragma unroll
            for (int v = tid; v < AV; v += THREADS) {
                int mr = v / (BK / 4);
                int c4 = (v % (BK / 4)) * 4;
                float4 f = *reinterpret_cast<const float4*>(
                    &A[(size_t)(m0 + mr) * lda + k0 + c4]);
                uint4 u = {f2tf(f.x), f2tf(f.y), f2tf(f.z), f2tf(f.w)};
                *reinterpret_cast<uint4*>(&As[mr * ASTRIDE + c4]) = u;
            }
        }
        // ---- load B tile (BK x BN, row-major) ----
        constexpr int BV = BK * (BN / 4);
        #pragma unroll
        for (int v = tid; v < BV; v += THREADS) {
            int kr = v / (BN / 4);
            int c4 = (v % (BN / 4)) * 4;
            float4 f = *reinterpret_cast<const float4*>(
                &Bmat[(size_t)(k0 + kr) * ldb + n0 + c4]);
            uint4 u = {f2tf(f.x), f2tf(f.y), f2tf(f.z), f2tf(f.w)};
            *reinterpret_cast<uint4*>(&Bs[kr * BSTRIDE + c4]) = u;
        }
        __syncthreads();

        #pragma unroll
        for (int ks = 0; ks < BK; ks += 8) {
            uint32_t af[MT][4], bf[NT][2];
            #pragma unroll
            for (int mt = 0; mt < MT; ++mt) {
                int row = wm + mt * 16 + g;
                if (TRANS_A) {
                    af[mt][0] = As[(ks + t) * ASTRIDE + row];
                    af[mt][1] = As[(ks + t) * ASTRIDE + row + 8];
                    af[mt][2] = As[(ks + t + 4) * ASTRIDE + row];
                    af[mt][3] = As[(ks + t + 4) * ASTRIDE + row + 8];
                } else {
                    af[mt][0] = As[row * ASTRIDE + ks + t];
                    af[mt][1] = As[(row + 8) * ASTRIDE + ks + t];
                    af[mt][2] = As[row * ASTRIDE + ks + t + 4];
                    af[mt][3] = As[(row + 8) * ASTRIDE + ks + t + 4];
                }
            }
            #pragma unroll
            for (int nt = 0; nt < NT; ++nt) {
                int col = wn + nt * 8 + g;
                bf[nt][0] = Bs[(ks + t) * BSTRIDE + col];
                bf[nt][1] = Bs[(ks + t + 4) * BSTRIDE + col];
            }
            #pragma unroll
            for (int mt = 0; mt < MT; ++mt)
                #pragma unroll
                for (int nt = 0; nt < NT; ++nt)
                    mma_tf32(acc[mt][nt], af[mt], bf[nt]);
        }
        __syncthreads();
    }

    // ---- epilogue ----
    #pragma unroll
    for (int mt = 0; mt < MT; ++mt) {
        int mg = m0 + wm + mt * 16 + g;
        float b0 = bias ? bias[mg] : 0.f;
        float b1 = bias ? bias[mg + 8] : 0.f;
        #pragma unroll
        for (int nt = 0; nt < NT; ++nt) {
            int n = n0 + wn + nt * 8 + 2 * t;
            float2 r0, r1;
            r0.x = acc[mt][nt][0] * scale + b0;
            r0.y = acc[mt][nt][1] * scale + b0;
            r1.x = acc[mt][nt][2] * scale + b1;
            r1.y = acc[mt][nt][3] * scale + b1;
            *reinterpret_cast<float2*>(&C[(size_t)mg * ldc + n]) = r0;
            *reinterpret_cast<float2*>(&C[(size_t)(mg + 8) * ldc + n]) = r1;
        }
    }
}

// ============================================================================
// In-place causal column softmax over k (row index). One thread per query q.
// ============================================================================
__global__ void softmax_causal(float* __restrict__ SC, const float* __restrict__ qk_mask,
                               const float* __restrict__ k_mask)
{
    const int z = blockIdx.y;      // b*H + h
    const int b = z / HH;
    const int q = blockIdx.x * blockDim.x + threadIdx.x;

    float* col        = SC + (size_t)z * SS * SS + q;
    const float* qm   = qk_mask + (size_t)b * SS * SS + q;  // [b, k, 0, q]
    const float* km   = k_mask + (size_t)b * SS;            // [b, k]

    float m = -1e30f, l = 0.f;
    for (int k = 0; k <= q; ++k) {
        float s  = col[(size_t)k * SS] + qm[(size_t)k * SS] + km[k];
        float mn = fmaxf(m, s);
        l = l * __expf(m - mn) + __expf(s - mn);
        m = mn;
    }
    const float inv = 1.f / l;
    for (int k = 0; k <= q; ++k) {
        float s = col[(size_t)k * SS] + qm[(size_t)k * SS] + km[k];
        col[(size_t)k * SS] = __expf(s - m) * inv;
    }
    const int kend = ((q >> 7) + 1) << 7;
    for (int k = q + 1; k < kend; ++k) col[(size_t)k * SS] = 0.f;
}

// ============================================================================
extern "C" void kernel_launch(void* const* d_in, const int* in_sizes, int n_in,
                              void* d_out, int out_size)
{
    (void)in_sizes; (void)n_in; (void)out_size;
    const float* q       = (const float*)d_in[0];
    const float* k       = (const float*)d_in[1];
    const float* v       = (const float*)d_in[2];
    const float* qk_mask = (const float*)d_in[3];
    const float* k_mask  = (const float*)d_in[4];
    const float* Wq = (const float*)d_in[5];
    const float* bq = (const float*)d_in[6];
    const float* Wk = (const float*)d_in[7];
    const float* bk = (const float*)d_in[8];
    const float* Wv = (const float*)d_in[9];
    const float* bv = (const float*)d_in[10];
    const float* Wo = (const float*)d_in[11];
    const float* bo = (const float*)d_in[12];
    float* out = (float*)d_out;

    float *QP, *KP, *VP, *SC, *AT;
    cudaGetSymbolAddress((void**)&QP, g_QP);
    cudaGetSymbolAddress((void**)&KP, g_KP);
    cudaGetSymbolAddress((void**)&VP, g_VP);
    cudaGetSymbolAddress((void**)&SC, g_SC);
    cudaGetSymbolAddress((void**)&AT, g_AT);

    const size_t sX = (size_t)EE * SS;   // per-batch input stride
    const size_t sP = (size_t)DD * SS;   // per-batch projection stride
    const size_t sH = (size_t)DH * SS;   // per-(b,h) head stride
    const size_t sS = (size_t)SS * SS;   // per-(b,h) score stride

    // 1) projections: QP/KP/VP[b, o, s] = W @ x_b + bias   (tf32 MMA)
    dim3 gp(SS / 128, DD / 128, BB);
    mma_gemm<128, 128, 2, 4, false, false, false><<<gp, 256>>>(
        Wq, q, bq, QP, EE, EE, SS, SS, 0, sX, sP, 1.0f);
    mma_gemm<128, 128, 2, 4, false, false, false><<<gp, 256>>>(
        Wk, k, bk, KP, EE, EE, SS, SS, 0, sX, sP, 1.0f);
    mma_gemm<128, 128, 2, 4, false, false, false><<<gp, 256>>>(
        Wv, v, bv, VP, EE, EE, SS, SS, 0, sX, sP, 1.0f);

    // 2) scores[z, kk, qq] = 1/8 * (K^T Q)   (causal blocks only, tf32 MMA)
    dim3 gs(SS / 128, SS / 128, BB * HH);
    mma_gemm<128, 128, 2, 4, true, true, false><<<gs, 256>>>(
        KP, QP, nullptr, SC, DH, SS, SS, SS, sH, sH, sS, 0.125f);

    // 3) causal softmax over k, in place (adds qk_mask + k_mask)
    softmax_causal<<<dim3(SS / 256, BB * HH), 256>>>(SC, qk_mask, k_mask);

    // 4) attn[z, c, qq] = V @ P   (K clamped causally, tf32 MMA)
    dim3 ga(SS / 128, 1, BB * HH);
    mma_gemm<64, 128, 2, 4, false, false, true><<<ga, 256>>>(
        VP, SC, nullptr, AT, SS, SS, SS, SS, sH, sS, sH, 1.0f);

    // 5) output projection (tf32 MMA)
    dim3 go(SS / 128, DD / 128, BB);
    mma_gemm<128, 128, 2, 4, false, false, false><<<go, 256>>>(
        Wo, AT, bo, out, DD, DD, SS, SS, 0, sP, sP, 1.0f);
}

// round 3
// speedup vs baseline: 2.7914x; 1.6500x over previous
#include <cuda_runtime.h>
#include <stdint.h>
#include <math.h>

#define BB 2
#define EE 1024
#define SS 2048
#define HH 16
#define DD 1024
#define DH 64

// ---- scratch (static __device__ arrays; no allocations allowed) ----
__device__ float g_QP[(size_t)BB * DD * SS];
__device__ float g_KP[(size_t)BB * DD * SS];
__device__ float g_VP[(size_t)BB * DD * SS];
__device__ float g_SC[(size_t)BB * HH * SS * SS];  // scores, softmaxed in place
__device__ float g_AT[(size_t)BB * DD * SS];

__device__ __forceinline__ uint32_t f2tf(float x) {
    uint32_t u;
    asm("cvt.rna.tf32.f32 %0, %1;" : "=r"(u) : "f"(x));
    return u;
}

__device__ __forceinline__ void mma_tf32(float* c, const uint32_t* a, const uint32_t* b) {
    asm volatile(
        "mma.sync.aligned.m16n8k8.row.col.f32.tf32.tf32.f32 "
        "{%0,%1,%2,%3}, {%4,%5,%6,%7}, {%8,%9}, {%0,%1,%2,%3};"
        : "+f"(c[0]), "+f"(c[1]), "+f"(c[2]), "+f"(c[3])
        : "r"(a[0]), "r"(a[1]), "r"(a[2]), "r"(a[3]), "r"(b[0]), "r"(b[1]));
}

__device__ __forceinline__ void cp16(void* smem, const void* gmem) {
    uint32_t s = (uint32_t)__cvta_generic_to_shared(smem);
    asm volatile("cp.async.cg.shared.global [%0], [%1], 16;\n" :: "r"(s), "l"(gmem));
}
__device__ __forceinline__ void cp_commit() { asm volatile("cp.async.commit_group;\n"); }
template <int N>
__device__ __forceinline__ void cp_wait() { asm volatile("cp.async.wait_group %0;\n" :: "n"(N)); }

// ============================================================================
// tf32 tensor-core block GEMM with 3-stage cp.async pipeline.
//   C[m,n] = scale * sum_k A*B (+ bias[m])
//   TRANS_A=false: A is MxK row-major;  true: A is KxM row-major (scores K^T Q)
//   CSKIP : skip blocks fully above causal diagonal (m=key, n=query)
//   CCLAMP: clamp K loop to n0+BN (attn = V @ P)
// Raw fp32 staged in smem; cvt.rna.tf32 applied at fragment load (numerics
// identical to cvt-at-store).
// ============================================================================
template <int BM, int BN, int WM, int WN, bool TRANS_A, bool CSKIP, bool CCLAMP>
__global__ void __launch_bounds__(WM * WN * 32, 2)
mma_gemm(const float* __restrict__ A, const float* __restrict__ Bmat,
         const float* __restrict__ bias, float* __restrict__ C,
         int K, int lda, int ldb, int ldc,
         size_t sA, size_t sB, size_t sC, float scale)
{
    constexpr int BK = 16;
    constexpr int THREADS = WM * WN * 32;
    constexpr int MT = BM / WM / 16;
    constexpr int NT = BN / WN / 8;
    constexpr int AST = TRANS_A ? (BM + 8) : 20;
    constexpr int ASZ = TRANS_A ? (BK * AST) : (BM * AST);
    constexpr int BST = BN + 8;
    constexpr int BSZ = BK * BST;
    constexpr int STG = 3;
    constexpr int AV = (TRANS_A ? BK * BM : BM * BK) / 4 / THREADS;
    constexpr int BV = BK * BN / 4 / THREADS;

    const int n0 = blockIdx.x * BN;
    const int m0 = blockIdx.y * BM;
    if (CSKIP && m0 > n0 + BN - 1) return;

    const int z = blockIdx.z;
    A    += (size_t)z * sA;
    Bmat += (size_t)z * sB;
    C    += (size_t)z * sC;

    const int Kend  = CCLAMP ? min(K, n0 + BN) : K;
    const int niter = Kend / BK;

    __shared__ __align__(16) float As[STG][ASZ];
    __shared__ __align__(16) float Bs[STG][BSZ];

    const int tid  = threadIdx.x;
    const int lane = tid & 31;
    const int wid  = tid >> 5;
    const int g    = lane >> 2;
    const int t    = lane & 3;
    const int wm   = (wid / WN) * (BM / WM);
    const int wn   = (wid % WN) * (BN / WN);

    auto issue = [&](int it, int s) {
        const int k0 = it * BK;
        #pragma unroll
        for (int j = 0; j < AV; ++j) {
            int v = tid + j * THREADS;
            if (TRANS_A) {
                int kr = v / (BM / 4), c4 = (v % (BM / 4)) * 4;
                cp16(&As[s][kr * AST + c4], &A[(size_t)(k0 + kr) * lda + m0 + c4]);
            } else {
                int mr = v / (BK / 4), c4 = (v % (BK / 4)) * 4;
                cp16(&As[s][mr * AST + c4], &A[(size_t)(m0 + mr) * lda + k0 + c4]);
            }
        }
        #pragma unroll
        for (int j = 0; j < BV; ++j) {
            int v = tid + j * THREADS;
            int kr = v / (BN / 4), c4 = (v % (BN / 4)) * 4;
            cp16(&Bs[s][kr * BST + c4], &Bmat[(size_t)(k0 + kr) * ldb + n0 + c4]);
        }
        cp_commit();
    };

    float acc[MT][NT][4] = {};

    issue(0, 0);
    if (niter > 1) issue(1, 1);

    for (int i = 0; i < niter; ++i) {
        const int cur = i % STG;
        // wait for tile i (FIFO group completion)
        if (i + 1 < niter) cp_wait<1>(); else cp_wait<0>();
        __syncthreads();  // tile i visible to all; compute(i-1) finished by all
        if (i + 2 < niter) issue(i + 2, (i + 2) % STG);  // buf (i-1)%STG, now free

        #pragma unroll
        for (int ks = 0; ks < BK; ks += 8) {
            uint32_t af[MT][4], bf[NT][2];
            #pragma unroll
            for (int mt = 0; mt < MT; ++mt) {
                int row = wm + mt * 16 + g;
                if (TRANS_A) {
                    af[mt][0] = f2tf(As[cur][(ks + t) * AST + row]);
                    af[mt][1] = f2tf(As[cur][(ks + t) * AST + row + 8]);
                    af[mt][2] = f2tf(As[cur][(ks + t + 4) * AST + row]);
                    af[mt][3] = f2tf(As[cur][(ks + t + 4) * AST + row + 8]);
                } else {
                    af[mt][0] = f2tf(As[cur][row * AST + ks + t]);
                    af[mt][1] = f2tf(As[cur][(row + 8) * AST + ks + t]);
                    af[mt][2] = f2tf(As[cur][row * AST + ks + t + 4]);
                    af[mt][3] = f2tf(As[cur][(row + 8) * AST + ks + t + 4]);
                }
            }
            #pragma unroll
            for (int nt = 0; nt < NT; ++nt) {
                int col = wn + nt * 8 + g;
                bf[nt][0] = f2tf(Bs[cur][(ks + t) * BST + col]);
                bf[nt][1] = f2tf(Bs[cur][(ks + t + 4) * BST + col]);
            }
            #pragma unroll
            for (int mt = 0; mt < MT; ++mt)
                #pragma unroll
                for (int nt = 0; nt < NT; ++nt)
                    mma_tf32(acc[mt][nt], af[mt], bf[nt]);
        }
        __syncthreads();  // compute(i) done before iter i+1 issues into buf i%STG
    }

    // ---- epilogue ----
    #pragma unroll
    for (int mt = 0; mt < MT; ++mt) {
        int mg = m0 + wm + mt * 16 + g;
        float b0 = bias ? bias[mg] : 0.f;
        float b1 = bias ? bias[mg + 8] : 0.f;
        #pragma unroll
        for (int nt = 0; nt < NT; ++nt) {
            int n = n0 + wn + nt * 8 + 2 * t;
            float2 r0, r1;
            r0.x = acc[mt][nt][0] * scale + b0;
            r0.y = acc[mt][nt][1] * scale + b0;
            r1.x = acc[mt][nt][2] * scale + b1;
            r1.y = acc[mt][nt][3] * scale + b1;
            *reinterpret_cast<float2*>(&C[(size_t)mg * ldc + n]) = r0;
            *reinterpret_cast<float2*>(&C[(size_t)(mg + 8) * ldc + n]) = r1;
        }
    }
}

// ============================================================================
// Block-parallel causal column softmax over k. Block = (32 q, 8 k-slices).
// Per-thread online (m,l) over strided k, smem tree combine, then one
// normalized-exp write pass; zero-fill to next 128-aligned row.
// ============================================================================
__global__ void softmax_causal(float* __restrict__ SC, const float* __restrict__ qk_mask,
                               const float* __restrict__ k_mask)
{
    const int z  = blockIdx.y;     // b*H + h
    const int b  = z / HH;
    const int qx = threadIdx.x;    // 0..31
    const int ky = threadIdx.y;    // 0..7
    const int q  = blockIdx.x * 32 + qx;

    float* col      = SC + (size_t)z * SS * SS + q;
    const float* qm = qk_mask + (size_t)b * SS * SS + q;  // [b, k, 0, q]
    const float* km = k_mask + (size_t)b * SS;            // [b, k]

    // pass 1: per-thread online max/sum over k = ky, ky+8, ..., <= q
    float m = -1e30f, l = 0.f;
    for (int k = ky; k <= q; k += 8) {
        float s  = col[(size_t)k * SS] + qm[(size_t)k * SS] + km[k];
        float mn = fmaxf(m, s);
        l = l * __expf(m - mn) + __expf(s - mn);
        m = mn;
    }

    __shared__ float sm[8][32], sl[8][32];
    sm[ky][qx] = m;
    sl[ky][qx] = l;
    __syncthreads();
    if (ky == 0) {
        float M = sm[0][qx], L = sl[0][qx];
        #pragma unroll
        for (int j = 1; j < 8; ++j) {
            float mj = sm[j][qx], lj = sl[j][qx];
            float mn = fmaxf(M, mj);
            L = L * __expf(M - mn) + lj * __expf(mj - mn);
            M = mn;
        }
        sm[0][qx] = M;
        sl[0][qx] = 1.f / L;
    }
    __syncthreads();
    const float M   = sm[0][qx];
    const float inv = sl[0][qx];

    // pass 2: write normalized probabilities
    for (int k = ky; k <= q; k += 8) {
        float s = col[(size_t)k * SS] + qm[(size_t)k * SS] + km[k];
        col[(size_t)k * SS] = __expf(s - M) * inv;
    }

    // zero-fill (q, next 128-aligned) so causal attn GEMM reads clean tiles
    const int kend   = ((q >> 7) + 1) << 7;
    const int kstart = (q + 1) + ((ky - (q + 1)) & 7);
    for (int k = kstart; k < kend; k += 8) col[(size_t)k * SS] = 0.f;
}

// ============================================================================
extern "C" void kernel_launch(void* const* d_in, const int* in_sizes, int n_in,
                              void* d_out, int out_size)
{
    (void)in_sizes; (void)n_in; (void)out_size;
    const float* q       = (const float*)d_in[0];
    const float* k       = (const float*)d_in[1];
    const float* v       = (const float*)d_in[2];
    const float* qk_mask = (const float*)d_in[3];
    const float* k_mask  = (const float*)d_in[4];
    const float* Wq = (const float*)d_in[5];
    const float* bq = (const float*)d_in[6];
    const float* Wk = (const float*)d_in[7];
    const float* bk = (const float*)d_in[8];
    const float* Wv = (const float*)d_in[9];
    const float* bv = (const float*)d_in[10];
    const float* Wo = (const float*)d_in[11];
    const float* bo = (const float*)d_in[12];
    float* out = (float*)d_out;

    float *QP, *KP, *VP, *SC, *AT;
    cudaGetSymbolAddress((void**)&QP, g_QP);
    cudaGetSymbolAddress((void**)&KP, g_KP);
    cudaGetSymbolAddress((void**)&VP, g_VP);
    cudaGetSymbolAddress((void**)&SC, g_SC);
    cudaGetSymbolAddress((void**)&AT, g_AT);

    const size_t sX = (size_t)EE * SS;   // per-batch input stride
    const size_t sP = (size_t)DD * SS;   // per-batch projection stride
    const size_t sH = (size_t)DH * SS;   // per-(b,h) head stride
    const size_t sS = (size_t)SS * SS;   // per-(b,h) score stride

    // 1) projections: QP/KP/VP[b, o, s] = W @ x_b + bias
    dim3 gp(SS / 128, DD / 128, BB);
    mma_gemm<128, 128, 2, 4, false, false, false><<<gp, 256>>>(
        Wq, q, bq, QP, EE, EE, SS, SS, 0, sX, sP, 1.0f);
    mma_gemm<128, 128, 2, 4, false, false, false><<<gp, 256>>>(
        Wk, k, bk, KP, EE, EE, SS, SS, 0, sX, sP, 1.0f);
    mma_gemm<128, 128, 2, 4, false, false, false><<<gp, 256>>>(
        Wv, v, bv, VP, EE, EE, SS, SS, 0, sX, sP, 1.0f);

    // 2) scores[z, kk, qq] = 1/8 * (K^T Q)   (causal blocks only)
    dim3 gs(SS / 128, SS / 128, BB * HH);
    mma_gemm<128, 128, 2, 4, true, true, false><<<gs, 256>>>(
        KP, QP, nullptr, SC, DH, SS, SS, SS, sH, sH, sS, 0.125f);

    // 3) causal softmax over k, in place (adds qk_mask + k_mask)
    softmax_causal<<<dim3(SS / 32, BB * HH), dim3(32, 8)>>>(SC, qk_mask, k_mask);

    // 4) attn[z, c, qq] = V @ P   (K clamped causally)
    dim3 ga(SS / 128, 1, BB * HH);
    mma_gemm<64, 128, 2, 4, false, false, true><<<ga, 256>>>(
        VP, SC, nullptr, AT, SS, SS, SS, SS, sH, sS, sH, 1.0f);

    // 5) output projection
    dim3 go(SS / 128, DD / 128, BB);
    mma_gemm<128, 128, 2, 4, false, false, false><<<go, 256>>>(
        Wo, AT, bo, out, DD, DD, SS, SS, 0, sP, sP, 1.0f);
}

// round 4
// speedup vs baseline: 4.0970x; 1.4677x over previous
#include <cuda_runtime.h>
#include <stdint.h>
#include <math.h>

#define BB 2
#define EE 1024
#define SS 2048
#define HH 16
#define DD 1024
#define DH 64
#define TQ 128
#define TK 64

// ---- scratch (static __device__ arrays; no allocations allowed) ----
__device__ float g_QP[(size_t)BB * DD * SS];
__device__ float g_KP[(size_t)BB * DD * SS];
__device__ float g_VP[(size_t)BB * DD * SS];
__device__ float g_AT[(size_t)BB * DD * SS];

__device__ __forceinline__ uint32_t f2tf(float x) {
    uint32_t u;
    asm("cvt.rna.tf32.f32 %0, %1;" : "=r"(u) : "f"(x));
    return u;
}

__device__ __forceinline__ void mma_tf32(float* c, const uint32_t* a, const uint32_t* b) {
    asm volatile(
        "mma.sync.aligned.m16n8k8.row.col.f32.tf32.tf32.f32 "
        "{%0,%1,%2,%3}, {%4,%5,%6,%7}, {%8,%9}, {%0,%1,%2,%3};"
        : "+f"(c[0]), "+f"(c[1]), "+f"(c[2]), "+f"(c[3])
        : "r"(a[0]), "r"(a[1]), "r"(a[2]), "r"(a[3]), "r"(b[0]), "r"(b[1]));
}

__device__ __forceinline__ void cp16(void* smem, const void* gmem) {
    uint32_t s = (uint32_t)__cvta_generic_to_shared(smem);
    asm volatile("cp.async.cg.shared.global [%0], [%1], 16;\n" :: "r"(s), "l"(gmem));
}
__device__ __forceinline__ void cp_commit() { asm volatile("cp.async.commit_group;\n"); }
template <int N>
__device__ __forceinline__ void cp_wait() { asm volatile("cp.async.wait_group %0;\n" :: "n"(N)); }

// ============================================================================
// tf32 tensor-core block GEMM with 3-stage cp.async pipeline (projections +
// output projection). Same as round 3.
// ============================================================================
template <int BM, int BN, int WM, int WN>
__global__ void __launch_bounds__(WM * WN * 32, 2)
mma_gemm(const float* __restrict__ A, const float* __restrict__ Bmat,
         const float* __restrict__ bias, float* __restrict__ C,
         int K, int lda, int ldb, int ldc,
         size_t sA, size_t sB, size_t sC)
{
    constexpr int BK = 16;
    constexpr int THREADS = WM * WN * 32;
    constexpr int MT = BM / WM / 16;
    constexpr int NT = BN / WN / 8;
    constexpr int AST = 20;
    constexpr int ASZ = BM * AST;
    constexpr int BST = BN + 8;
    constexpr int BSZ = BK * BST;
    constexpr int STG = 3;
    constexpr int AV = BM * BK / 4 / THREADS;
    constexpr int BV = BK * BN / 4 / THREADS;

    const int n0 = blockIdx.x * BN;
    const int m0 = blockIdx.y * BM;
    const int z = blockIdx.z;
    A    += (size_t)z * sA;
    Bmat += (size_t)z * sB;
    C    += (size_t)z * sC;

    const int niter = K / BK;

    __shared__ __align__(16) float As[STG][ASZ];
    __shared__ __align__(16) float Bs[STG][BSZ];

    const int tid  = threadIdx.x;
    const int lane = tid & 31;
    const int wid  = tid >> 5;
    const int g    = lane >> 2;
    const int t    = lane & 3;
    const int wm   = (wid / WN) * (BM / WM);
    const int wn   = (wid % WN) * (BN / WN);

    auto issue = [&](int it, int s) {
        const int k0 = it * BK;
        #pragma unroll
        for (int j = 0; j < AV; ++j) {
            int v = tid + j * THREADS;
            int mr = v / (BK / 4), c4 = (v % (BK / 4)) * 4;
            cp16(&As[s][mr * AST + c4], &A[(size_t)(m0 + mr) * lda + k0 + c4]);
        }
        #pragma unroll
        for (int j = 0; j < BV; ++j) {
            int v = tid + j * THREADS;
            int kr = v / (BN / 4), c4 = (v % (BN / 4)) * 4;
            cp16(&Bs[s][kr * BST + c4], &Bmat[(size_t)(k0 + kr) * ldb + n0 + c4]);
        }
        cp_commit();
    };

    float acc[MT][NT][4] = {};

    issue(0, 0);
    if (niter > 1) issue(1, 1);

    for (int i = 0; i < niter; ++i) {
        const int cur = i % STG;
        if (i + 1 < niter) cp_wait<1>(); else cp_wait<0>();
        __syncthreads();
        if (i + 2 < niter) issue(i + 2, (i + 2) % STG);

        #pragma unroll
        for (int ks = 0; ks < BK; ks += 8) {
            uint32_t af[MT][4], bf[NT][2];
            #pragma unroll
            for (int mt = 0; mt < MT; ++mt) {
                int row = wm + mt * 16 + g;
                af[mt][0] = f2tf(As[cur][row * AST + ks + t]);
                af[mt][1] = f2tf(As[cur][(row + 8) * AST + ks + t]);
                af[mt][2] = f2tf(As[cur][row * AST + ks + t + 4]);
                af[mt][3] = f2tf(As[cur][(row + 8) * AST + ks + t + 4]);
            }
            #pragma unroll
            for (int nt = 0; nt < NT; ++nt) {
                int col = wn + nt * 8 + g;
                bf[nt][0] = f2tf(Bs[cur][(ks + t) * BST + col]);
                bf[nt][1] = f2tf(Bs[cur][(ks + t + 4) * BST + col]);
            }
            #pragma unroll
            for (int mt = 0; mt < MT; ++mt)
                #pragma unroll
                for (int nt = 0; nt < NT; ++nt)
                    mma_tf32(acc[mt][nt], af[mt], bf[nt]);
        }
        __syncthreads();
    }

    #pragma unroll
    for (int mt = 0; mt < MT; ++mt) {
        int mg = m0 + wm + mt * 16 + g;
        float b0 = bias ? bias[mg] : 0.f;
        float b1 = bias ? bias[mg + 8] : 0.f;
        #pragma unroll
        for (int nt = 0; nt < NT; ++nt) {
            int n = n0 + wn + nt * 8 + 2 * t;
            float2 r0, r1;
            r0.x = acc[mt][nt][0] + b0;
            r0.y = acc[mt][nt][1] + b0;
            r1.x = acc[mt][nt][2] + b1;
            r1.y = acc[mt][nt][3] + b1;
            *reinterpret_cast<float2*>(&C[(size_t)mg * ldc + n]) = r0;
            *reinterpret_cast<float2*>(&C[(size_t)(mg + 8) * ldc + n]) = r1;
        }
    }
}

// ============================================================================
// Fused flash attention over projected heads.
// Block = one (b*H+h, q-tile of 128). 256 threads, 8 warps (2 m-halves x 4).
// Per k-tile (64): S = 1/8 K^T Q (tf32 MMA) + qk_mask + k_mask; online
// column softmax (shfl over g + smem combine of the 2 m-halves); P -> smem;
// O += V @ P (tf32 MMA). Epilogue: O / l -> AT.
// smem strides chosen conflict-free per access pattern:
//   Ks[c][k] st 72 (frag [t][g]), Vs[c][k] st 68 (frag [g][t]),
//   Qs/Ps st 136 (frag [t][g]).
// ============================================================================
__global__ void __launch_bounds__(256, 2)
flash_attn(const float* __restrict__ QP, const float* __restrict__ KP,
           const float* __restrict__ VP, const float* __restrict__ qk_mask,
           const float* __restrict__ k_mask, float* __restrict__ AT)
{
    extern __shared__ __align__(16) float smf[];
    float* Qs  = smf;                  // [64][136]
    float* Ks  = Qs + 64 * 136;       // [64][72]
    float* Vs  = Ks + 64 * 72;        // [64][68]
    float* Ps  = Vs + 64 * 68;        // [64][136]
    float* red = Ps + 64 * 136;       // [2][128]

    const int z   = blockIdx.y;       // b*H + h
    const int b   = z / HH;
    const int q0  = blockIdx.x * TQ;
    const int tid = threadIdx.x;
    const int lane = tid & 31;
    const int wid  = tid >> 5;
    const int g = lane >> 2;
    const int t = lane & 3;
    const int mh = wid >> 2;          // m-half: 0/1
    const int wm = mh * 32;
    const int wn = (wid & 3) * 32;

    const float* Qg = QP + (size_t)z * DH * SS;
    const float* Kg = KP + (size_t)z * DH * SS;
    const float* Vg = VP + (size_t)z * DH * SS;
    const float* qm = qk_mask + (size_t)b * SS * SS;
    const float* km = k_mask + (size_t)b * SS;

    // load Q tile once: [c=64][q=128]
    #pragma unroll
    for (int j = 0; j < 8; ++j) {
        int v = tid + j * 256;
        int r = v >> 5, c4 = (v & 31) << 2;
        cp16(&Qs[r * 136 + c4], &Qg[(size_t)r * SS + q0 + c4]);
    }
    cp_commit();

    float accO[2][4][4] = {};
    float mC[8], lC[8];
    #pragma unroll
    for (int i = 0; i < 8; ++i) { mC[i] = -1e30f; lC[i] = 0.f; }

    const int nkt = (q0 + TQ) / TK;
    for (int kt = 0; kt < nkt; ++kt) {
        const int k0 = kt * TK;
        __syncthreads();   // prev MMA2 done; Ks/Vs/Ps/red free
        #pragma unroll
        for (int j = 0; j < 4; ++j) {
            int v = tid + j * 256;
            int r = v >> 4, c4 = (v & 15) << 2;
            cp16(&Ks[r * 72 + c4], &Kg[(size_t)r * SS + k0 + c4]);
        }
        #pragma unroll
        for (int j = 0; j < 4; ++j) {
            int v = tid + j * 256;
            int r = v >> 4, c4 = (v & 15) << 2;
            cp16(&Vs[r * 68 + c4], &Vg[(size_t)r * SS + k0 + c4]);
        }
        cp_commit();
        cp_wait<0>();
        __syncthreads();

        // ---- MMA1: S[k][q] = K^T Q ----
        float acc[2][4][4] = {};
        #pragma unroll
        for (int ks = 0; ks < DH; ks += 8) {
            uint32_t af[2][4], bf[4][2];
            #pragma unroll
            for (int mt = 0; mt < 2; ++mt) {
                int row = wm + mt * 16 + g;
                af[mt][0] = f2tf(Ks[(ks + t) * 72 + row]);
                af[mt][1] = f2tf(Ks[(ks + t) * 72 + row + 8]);
                af[mt][2] = f2tf(Ks[(ks + t + 4) * 72 + row]);
                af[mt][3] = f2tf(Ks[(ks + t + 4) * 72 + row + 8]);
            }
            #pragma unroll
            for (int nt = 0; nt < 4; ++nt) {
                int col = wn + nt * 8 + g;
                bf[nt][0] = f2tf(Qs[(ks + t) * 136 + col]);
                bf[nt][1] = f2tf(Qs[(ks + t + 4) * 136 + col]);
            }
            #pragma unroll
            for (int mt = 0; mt < 2; ++mt)
                #pragma unroll
                for (int nt = 0; nt < 4; ++nt)
                    mma_tf32(acc[mt][nt], af[mt], bf[nt]);
        }

        // ---- scale + masks; per-column tile max ----
        float pmax[8];
        #pragma unroll
        for (int i = 0; i < 8; ++i) pmax[i] = -1e30f;
        #pragma unroll
        for (int mt = 0; mt < 2; ++mt) {
            int rk = k0 + wm + mt * 16 + g;
            float km0 = __ldg(&km[rk]);
            float km1 = __ldg(&km[rk + 8]);
            #pragma unroll
            for (int nt = 0; nt < 4; ++nt) {
                int cq = q0 + wn + nt * 8 + 2 * t;
                float2 m0 = *reinterpret_cast<const float2*>(&qm[(size_t)rk * SS + cq]);
                float2 m1 = *reinterpret_cast<const float2*>(&qm[(size_t)(rk + 8) * SS + cq]);
                acc[mt][nt][0] = fmaf(acc[mt][nt][0], 0.125f, m0.x + km0);
                acc[mt][nt][1] = fmaf(acc[mt][nt][1], 0.125f, m0.y + km0);
                acc[mt][nt][2] = fmaf(acc[mt][nt][2], 0.125f, m1.x + km1);
                acc[mt][nt][3] = fmaf(acc[mt][nt][3], 0.125f, m1.y + km1);
                pmax[nt * 2 + 0] = fmaxf(pmax[nt * 2 + 0], fmaxf(acc[mt][nt][0], acc[mt][nt][2]));
                pmax[nt * 2 + 1] = fmaxf(pmax[nt * 2 + 1], fmaxf(acc[mt][nt][1], acc[mt][nt][3]));
            }
        }
        #pragma unroll
        for (int off = 4; off <= 16; off <<= 1)
            #pragma unroll
            for (int i = 0; i < 8; ++i)
                pmax[i] = fmaxf(pmax[i], __shfl_xor_sync(0xffffffffu, pmax[i], off));
        if (g == 0) {
            #pragma unroll
            for (int nt = 0; nt < 4; ++nt) {
                red[mh * 128 + wn + nt * 8 + 2 * t]     = pmax[nt * 2];
                red[mh * 128 + wn + nt * 8 + 2 * t + 1] = pmax[nt * 2 + 1];
            }
        }
        __syncthreads();

        float fac[8];
        #pragma unroll
        for (int nt = 0; nt < 4; ++nt) {
            #pragma unroll
            for (int j2 = 0; j2 < 2; ++j2) {
                int col = wn + nt * 8 + 2 * t + j2;
                int i = nt * 2 + j2;
                float tm = fmaxf(red[col], red[128 + col]);
                float mn = fmaxf(mC[i], tm);
                fac[i] = __expf(mC[i] - mn);
                mC[i] = mn;
                lC[i] *= fac[i];
            }
        }
        #pragma unroll
        for (int mto = 0; mto < 2; ++mto)
            #pragma unroll
            for (int nt = 0; nt < 4; ++nt) {
                accO[mto][nt][0] *= fac[nt * 2];
                accO[mto][nt][1] *= fac[nt * 2 + 1];
                accO[mto][nt][2] *= fac[nt * 2];
                accO[mto][nt][3] *= fac[nt * 2 + 1];
            }

        // ---- P = exp(S - m) -> Ps; per-column partial sums ----
        float psum[8] = {};
        #pragma unroll
        for (int mt = 0; mt < 2; ++mt) {
            int rk = wm + mt * 16 + g;
            #pragma unroll
            for (int nt = 0; nt < 4; ++nt) {
                int col = wn + nt * 8 + 2 * t;
                float p0 = __expf(acc[mt][nt][0] - mC[nt * 2]);
                float p1 = __expf(acc[mt][nt][1] - mC[nt * 2 + 1]);
                float p2 = __expf(acc[mt][nt][2] - mC[nt * 2]);
                float p3 = __expf(acc[mt][nt][3] - mC[nt * 2 + 1]);
                psum[nt * 2]     += p0 + p2;
                psum[nt * 2 + 1] += p1 + p3;
                *reinterpret_cast<float2*>(&Ps[rk * 136 + col])       = make_float2(p0, p1);
                *reinterpret_cast<float2*>(&Ps[(rk + 8) * 136 + col]) = make_float2(p2, p3);
            }
        }
        #pragma unroll
        for (int off = 4; off <= 16; off <<= 1)
            #pragma unroll
            for (int i = 0; i < 8; ++i)
                psum[i] += __shfl_xor_sync(0xffffffffu, psum[i], off);
        if (g == 0) {
            #pragma unroll
            for (int nt = 0; nt < 4; ++nt) {
                red[mh * 128 + wn + nt * 8 + 2 * t]     = psum[nt * 2];
                red[mh * 128 + wn + nt * 8 + 2 * t + 1] = psum[nt * 2 + 1];
            }
        }
        __syncthreads();   // Ps complete + sums visible
        #pragma unroll
        for (int nt = 0; nt < 4; ++nt) {
            #pragma unroll
            for (int j2 = 0; j2 < 2; ++j2) {
                int col = wn + nt * 8 + 2 * t + j2;
                lC[nt * 2 + j2] += red[col] + red[128 + col];
            }
        }

        // ---- MMA2: O[c][q] += V @ P ----
        #pragma unroll
        for (int ks = 0; ks < TK; ks += 8) {
            uint32_t af[2][4], bf[4][2];
            #pragma unroll
            for (int mto = 0; mto < 2; ++mto) {
                int row = wm + mto * 16 + g;
                af[mto][0] = f2tf(Vs[row * 68 + ks + t]);
                af[mto][1] = f2tf(Vs[(row + 8) * 68 + ks + t]);
                af[mto][2] = f2tf(Vs[row * 68 + ks + t + 4]);
                af[mto][3] = f2tf(Vs[(row + 8) * 68 + ks + t + 4]);
            }
            #pragma unroll
            for (int nt = 0; nt < 4; ++nt) {
                int col = wn + nt * 8 + g;
                bf[nt][0] = f2tf(Ps[(ks + t) * 136 + col]);
                bf[nt][1] = f2tf(Ps[(ks + t + 4) * 136 + col]);
            }
            #pragma unroll
            for (int mto = 0; mto < 2; ++mto)
                #pragma unroll
                for (int nt = 0; nt < 4; ++nt)
                    mma_tf32(accO[mto][nt], af[mto], bf[nt]);
        }
    }

    // ---- epilogue: O / l -> AT ----
    float* ATz = AT + (size_t)z * DH * SS;
    #pragma unroll
    for (int mto = 0; mto < 2; ++mto) {
        int rc = wm + mto * 16 + g;
        #pragma unroll
        for (int nt = 0; nt < 4; ++nt) {
            int col = q0 + wn + nt * 8 + 2 * t;
            float i0 = 1.f / lC[nt * 2];
            float i1 = 1.f / lC[nt * 2 + 1];
            float2 r0, r1;
            r0.x = accO[mto][nt][0] * i0;
            r0.y = accO[mto][nt][1] * i1;
            r1.x = accO[mto][nt][2] * i0;
            r1.y = accO[mto][nt][3] * i1;
            *reinterpret_cast<float2*>(&ATz[(size_t)rc * SS + col]) = r0;
            *reinterpret_cast<float2*>(&ATz[(size_t)(rc + 8) * SS + col]) = r1;
        }
    }
}

// ============================================================================
extern "C" void kernel_launch(void* const* d_in, const int* in_sizes, int n_in,
                              void* d_out, int out_size)
{
    (void)in_sizes; (void)n_in; (void)out_size;
    const float* q       = (const float*)d_in[0];
    const float* k       = (const float*)d_in[1];
    const float* v       = (const float*)d_in[2];
    const float* qk_mask = (const float*)d_in[3];
    const float* k_mask  = (const float*)d_in[4];
    const float* Wq = (const float*)d_in[5];
    const float* bq = (const float*)d_in[6];
    const float* Wk = (const float*)d_in[7];
    const float* bk = (const float*)d_in[8];
    const float* Wv = (const float*)d_in[9];
    const float* bv = (const float*)d_in[10];
    const float* Wo = (const float*)d_in[11];
    const float* bo = (const float*)d_in[12];
    float* out = (float*)d_out;

    float *QP, *KP, *VP, *AT;
    cudaGetSymbolAddress((void**)&QP, g_QP);
    cudaGetSymbolAddress((void**)&KP, g_KP);
    cudaGetSymbolAddress((void**)&VP, g_VP);
    cudaGetSymbolAddress((void**)&AT, g_AT);

    const size_t sX = (size_t)EE * SS;
    const size_t sP = (size_t)DD * SS;

    // 1) projections
    dim3 gp(SS / 128, DD / 128, BB);
    mma_gemm<128, 128, 2, 4><<<gp, 256>>>(Wq, q, bq, QP, EE, EE, SS, SS, 0, sX, sP);
    mma_gemm<128, 128, 2, 4><<<gp, 256>>>(Wk, k, bk, KP, EE, EE, SS, SS, 0, sX, sP);
    mma_gemm<128, 128, 2, 4><<<gp, 256>>>(Wv, v, bv, VP, EE, EE, SS, SS, 0, sX, sP);

    // 2) fused flash attention (scores + softmax + attn)
    const int FL_SMEM = (64 * 136 + 64 * 72 + 64 * 68 + 64 * 136 + 256) * 4;
    cudaFuncSetAttribute(flash_attn, cudaFuncAttributeMaxDynamicSharedMemorySize, FL_SMEM);
    flash_attn<<<dim3(SS / TQ, BB * HH), 256, FL_SMEM>>>(QP, KP, VP, qk_mask, k_mask, AT);

    // 3) output projection
    dim3 go(SS / 128, DD / 128, BB);
    mma_gemm<128, 128, 2, 4><<<go, 256>>>(Wo, AT, bo, out, DD, DD, SS, SS, 0, sP, sP);
}

// round 5
// speedup vs baseline: 4.3064x; 1.0511x over previous
#include <cuda_runtime.h>
#include <stdint.h>
#include <math.h>

#define BB 2
#define EE 1024
#define SS 2048
#define HH 16
#define DD 1024
#define DH 64
#define TQ 64
#define TK 32

// ---- scratch (static __device__ arrays; no allocations allowed) ----
__device__ float g_QP[(size_t)BB * DD * SS];
__device__ float g_KP[(size_t)BB * DD * SS];
__device__ float g_VP[(size_t)BB * DD * SS];
__device__ float g_AT[(size_t)BB * DD * SS];

__device__ __forceinline__ uint32_t f2tf(float x) {
    uint32_t u;
    asm("cvt.rna.tf32.f32 %0, %1;" : "=r"(u) : "f"(x));
    return u;
}

__device__ __forceinline__ void mma_tf32(float* c, const uint32_t* a, const uint32_t* b) {
    asm volatile(
        "mma.sync.aligned.m16n8k8.row.col.f32.tf32.tf32.f32 "
        "{%0,%1,%2,%3}, {%4,%5,%6,%7}, {%8,%9}, {%0,%1,%2,%3};"
        : "+f"(c[0]), "+f"(c[1]), "+f"(c[2]), "+f"(c[3])
        : "r"(a[0]), "r"(a[1]), "r"(a[2]), "r"(a[3]), "r"(b[0]), "r"(b[1]));
}

__device__ __forceinline__ void cp16(void* smem, const void* gmem) {
    uint32_t s = (uint32_t)__cvta_generic_to_shared(smem);
    asm volatile("cp.async.cg.shared.global [%0], [%1], 16;\n" :: "r"(s), "l"(gmem));
}
__device__ __forceinline__ void cp_commit() { asm volatile("cp.async.commit_group;\n"); }
template <int N>
__device__ __forceinline__ void cp_wait() { asm volatile("cp.async.wait_group %0;\n" :: "n"(N)); }

// ============================================================================
// Shared tf32 GEMM core: C[m,n] = sum_k A[m,k]*B[k,n] + bias[m].
// 128x128x16 tiles, 3-stage cp.async pipeline, 8 warps (2x4), 64x32 warp tile.
// ============================================================================
template <int BM, int BN>
__device__ __forceinline__ void gemm_core(
    const float* __restrict__ A, const float* __restrict__ Bmat,
    const float* __restrict__ bias, float* __restrict__ C,
    int K, int lda, int ldb, int ldc, int m0, int n0)
{
    constexpr int BK = 16;
    constexpr int THREADS = 256;
    constexpr int MT = 4, NT = 4;
    constexpr int AST = 20;
    constexpr int BST = BN + 8;
    constexpr int STG = 3;
    constexpr int AV = BM * BK / 4 / THREADS;
    constexpr int BV = BK * BN / 4 / THREADS;

    const int niter = K / BK;

    __shared__ __align__(16) float As[STG][BM * AST];
    __shared__ __align__(16) float Bs[STG][BK * BST];

    const int tid  = threadIdx.x;
    const int lane = tid & 31;
    const int wid  = tid >> 5;
    const int g    = lane >> 2;
    const int t    = lane & 3;
    const int wm   = (wid >> 2) * 64;
    const int wn   = (wid & 3) * 32;

    auto issue = [&](int it, int s) {
        const int k0 = it * BK;
        #pragma unroll
        for (int j = 0; j < AV; ++j) {
            int v = tid + j * THREADS;
            int mr = v / (BK / 4), c4 = (v % (BK / 4)) * 4;
            cp16(&As[s][mr * AST + c4], &A[(size_t)(m0 + mr) * lda + k0 + c4]);
        }
        #pragma unroll
        for (int j = 0; j < BV; ++j) {
            int v = tid + j * THREADS;
            int kr = v / (BN / 4), c4 = (v % (BN / 4)) * 4;
            cp16(&Bs[s][kr * BST + c4], &Bmat[(size_t)(k0 + kr) * ldb + n0 + c4]);
        }
        cp_commit();
    };

    float acc[MT][NT][4] = {};

    issue(0, 0);
    if (niter > 1) issue(1, 1);

    for (int i = 0; i < niter; ++i) {
        const int cur = i % STG;
        if (i + 1 < niter) cp_wait<1>(); else cp_wait<0>();
        __syncthreads();
        if (i + 2 < niter) issue(i + 2, (i + 2) % STG);

        #pragma unroll
        for (int ks = 0; ks < BK; ks += 8) {
            uint32_t af[MT][4], bf[NT][2];
            #pragma unroll
            for (int mt = 0; mt < MT; ++mt) {
                int row = wm + mt * 16 + g;
                af[mt][0] = f2tf(As[cur][row * AST + ks + t]);
                af[mt][1] = f2tf(As[cur][(row + 8) * AST + ks + t]);
                af[mt][2] = f2tf(As[cur][row * AST + ks + t + 4]);
                af[mt][3] = f2tf(As[cur][(row + 8) * AST + ks + t + 4]);
            }
            #pragma unroll
            for (int nt = 0; nt < NT; ++nt) {
                int col = wn + nt * 8 + g;
                bf[nt][0] = f2tf(Bs[cur][(ks + t) * BST + col]);
                bf[nt][1] = f2tf(Bs[cur][(ks + t + 4) * BST + col]);
            }
            #pragma unroll
            for (int mt = 0; mt < MT; ++mt)
                #pragma unroll
                for (int nt = 0; nt < NT; ++nt)
                    mma_tf32(acc[mt][nt], af[mt], bf[nt]);
        }
        __syncthreads();
    }

    #pragma unroll
    for (int mt = 0; mt < MT; ++mt) {
        int mg = m0 + wm + mt * 16 + g;
        float b0 = bias ? bias[mg] : 0.f;
        float b1 = bias ? bias[mg + 8] : 0.f;
        #pragma unroll
        for (int nt = 0; nt < NT; ++nt) {
            int n = n0 + wn + nt * 8 + 2 * t;
            float2 r0, r1;
            r0.x = acc[mt][nt][0] + b0;
            r0.y = acc[mt][nt][1] + b0;
            r1.x = acc[mt][nt][2] + b1;
            r1.y = acc[mt][nt][3] + b1;
            *reinterpret_cast<float2*>(&C[(size_t)mg * ldc + n]) = r0;
            *reinterpret_cast<float2*>(&C[(size_t)(mg + 8) * ldc + n]) = r1;
        }
    }
}

struct QKVParams {
    const float* W[3];
    const float* bias[3];
    const float* X[3];
    float* C[3];
};

// merged Q/K/V projections: z = mat*2 + batch
__global__ void __launch_bounds__(256, 2)
qkv_gemm(QKVParams p)
{
    const int mat = blockIdx.z >> 1;
    const int b   = blockIdx.z & 1;
    gemm_core<128, 128>(p.W[mat], p.X[mat] + (size_t)b * EE * SS, p.bias[mat],
                        p.C[mat] + (size_t)b * DD * SS,
                        EE, EE, SS, SS, blockIdx.y * 128, blockIdx.x * 128);
}

// output projection
__global__ void __launch_bounds__(256, 2)
out_gemm(const float* __restrict__ Wo, const float* __restrict__ AT,
         const float* __restrict__ bo, float* __restrict__ out)
{
    const int b = blockIdx.z;
    gemm_core<128, 128>(Wo, AT + (size_t)b * DD * SS, bo,
                        out + (size_t)b * DD * SS,
                        DD, DD, SS, SS, blockIdx.y * 128, blockIdx.x * 128);
}

// ============================================================================
// Fused flash attention. Block = (b*H+h, q-tile of 64). 256 threads, 8 warps.
// Double-buffered K/V (TK=32) via cp.async: tile kt+1 issued right after the
// top-of-iteration sync, overlapping all of compute(kt).
// qk_mask read only on diagonal tiles (k0+TK > q0); k_mask always added.
// Conflict-free smem strides: Qs/Ps 72, Ks 40, Vs 36.
// ============================================================================
__global__ void __launch_bounds__(256, 2)
flash_attn(const float* __restrict__ QP, const float* __restrict__ KP,
           const float* __restrict__ VP, const float* __restrict__ qk_mask,
           const float* __restrict__ k_mask, float* __restrict__ AT)
{
    extern __shared__ __align__(16) float smf[];
    float* Qs = smf;                       // [64 c][64 q] st 72
    float* Ks = Qs + 64 * 72;              // 2 x [64 c][32 k] st 40
    float* Vs = Ks + 2 * 64 * 40;          // 2 x [64 c][32 k] st 36
    float* Ps = Vs + 2 * 64 * 36;          // [32 k][64 q] st 72
    float* red = Ps + 32 * 72;             // [2][64]

    const int z   = blockIdx.y;
    const int b   = z / HH;
    const int q0  = blockIdx.x * TQ;
    const int tid  = threadIdx.x;
    const int lane = tid & 31;
    const int wid  = tid >> 5;
    const int g  = lane >> 2;
    const int t  = lane & 3;
    const int mh = wid >> 2;               // 0/1
    const int wq = (wid & 3) * 16;
    const int wk = mh * 16;                // MMA1 k-half
    const int wc = mh * 32;                // MMA2 c-half

    const float* Qg = QP + (size_t)z * DH * SS;
    const float* Kg = KP + (size_t)z * DH * SS;
    const float* Vg = VP + (size_t)z * DH * SS;
    const float* qm = qk_mask + (size_t)b * SS * SS;
    const float* km = k_mask + (size_t)b * SS;

    // Q tile: 64 rows x 64 cols
    #pragma unroll
    for (int j = 0; j < 4; ++j) {
        int v = tid + j * 256;
        int r = v >> 4, c4 = (v & 15) << 2;
        cp16(&Qs[r * 72 + c4], &Qg[(size_t)r * SS + q0 + c4]);
    }
    cp_commit();

    auto issue = [&](int kt, int s) {
        const int k0 = kt * TK;
        #pragma unroll
        for (int j = 0; j < 2; ++j) {
            int v = tid + j * 256;
            int r = v >> 3, c4 = (v & 7) << 2;
            cp16(&Ks[s * 64 * 40 + r * 40 + c4], &Kg[(size_t)r * SS + k0 + c4]);
            cp16(&Vs[s * 64 * 36 + r * 36 + c4], &Vg[(size_t)r * SS + k0 + c4]);
        }
        cp_commit();
    };

    float accO[2][2][4] = {};
    float mC[4], lC[4];
    #pragma unroll
    for (int i = 0; i < 4; ++i) { mC[i] = -1e30f; lC[i] = 0.f; }

    const int nkt = q0 / TK + 2;
    issue(0, 0);

    for (int kt = 0; kt < nkt; ++kt) {
        const int cur = kt & 1;
        const int k0  = kt * TK;
        const float* Kc = Ks + cur * 64 * 40;
        const float* Vc = Vs + cur * 64 * 36;

        cp_wait<0>();
        __syncthreads();                        // tile kt ready; iter kt-1 fully done
        if (kt + 1 < nkt) issue(kt + 1, cur ^ 1);

        // ---- MMA1: S[k=32][q=64] = K^T Q ----
        float acc[2][4] = {};
        #pragma unroll
        for (int ks = 0; ks < DH; ks += 8) {
            uint32_t af[4], bf[2][2];
            af[0] = f2tf(Kc[(ks + t) * 40 + wk + g]);
            af[1] = f2tf(Kc[(ks + t) * 40 + wk + g + 8]);
            af[2] = f2tf(Kc[(ks + t + 4) * 40 + wk + g]);
            af[3] = f2tf(Kc[(ks + t + 4) * 40 + wk + g + 8]);
            #pragma unroll
            for (int nt = 0; nt < 2; ++nt) {
                int col = wq + nt * 8 + g;
                bf[nt][0] = f2tf(Qs[(ks + t) * 72 + col]);
                bf[nt][1] = f2tf(Qs[(ks + t + 4) * 72 + col]);
            }
            mma_tf32(acc[0], af, bf[0]);
            mma_tf32(acc[1], af, bf[1]);
        }

        // ---- scale + masks; tile max ----
        const int rk0 = k0 + wk + g;
        const float km0 = __ldg(&km[rk0]);
        const float km1 = __ldg(&km[rk0 + 8]);
        float pmax[4];
        const bool diag = (k0 + TK > q0);
        #pragma unroll
        for (int nt = 0; nt < 2; ++nt) {
            int cq = q0 + wq + nt * 8 + 2 * t;
            float a0 = km0, a1 = km0, a2 = km1, a3 = km1;
            if (diag) {
                float2 m0 = *reinterpret_cast<const float2*>(&qm[(size_t)rk0 * SS + cq]);
                float2 m1 = *reinterpret_cast<const float2*>(&qm[(size_t)(rk0 + 8) * SS + cq]);
                a0 += m0.x; a1 += m0.y; a2 += m1.x; a3 += m1.y;
            }
            acc[nt][0] = fmaf(acc[nt][0], 0.125f, a0);
            acc[nt][1] = fmaf(acc[nt][1], 0.125f, a1);
            acc[nt][2] = fmaf(acc[nt][2], 0.125f, a2);
            acc[nt][3] = fmaf(acc[nt][3], 0.125f, a3);
            pmax[nt * 2]     = fmaxf(acc[nt][0], acc[nt][2]);
            pmax[nt * 2 + 1] = fmaxf(acc[nt][1], acc[nt][3]);
        }
        #pragma unroll
        for (int off = 4; off <= 16; off <<= 1)
            #pragma unroll
            for (int i = 0; i < 4; ++i)
                pmax[i] = fmaxf(pmax[i], __shfl_xor_sync(0xffffffffu, pmax[i], off));
        if (g == 0) {
            #pragma unroll
            for (int i = 0; i < 4; ++i)
                red[mh * 64 + wq + (i >> 1) * 8 + 2 * t + (i & 1)] = pmax[i];
        }
        __syncthreads();

        float fac[4];
        #pragma unroll
        for (int i = 0; i < 4; ++i) {
            int col = wq + (i >> 1) * 8 + 2 * t + (i & 1);
            float tm = fmaxf(red[col], red[64 + col]);
            float mn = fmaxf(mC[i], tm);
            fac[i] = __expf(mC[i] - mn);
            mC[i] = mn;
            lC[i] *= fac[i];
        }
        #pragma unroll
        for (int mto = 0; mto < 2; ++mto)
            #pragma unroll
            for (int nt = 0; nt < 2; ++nt) {
                accO[mto][nt][0] *= fac[nt * 2];
                accO[mto][nt][1] *= fac[nt * 2 + 1];
                accO[mto][nt][2] *= fac[nt * 2];
                accO[mto][nt][3] *= fac[nt * 2 + 1];
            }

        // ---- P = exp(S - m) -> Ps; partial sums ----
        float psum[4];
        #pragma unroll
        for (int nt = 0; nt < 2; ++nt) {
            int col = wq + nt * 8 + 2 * t;
            float p0 = __expf(acc[nt][0] - mC[nt * 2]);
            float p1 = __expf(acc[nt][1] - mC[nt * 2 + 1]);
            float p2 = __expf(acc[nt][2] - mC[nt * 2]);
            float p3 = __expf(acc[nt][3] - mC[nt * 2 + 1]);
            psum[nt * 2]     = p0 + p2;
            psum[nt * 2 + 1] = p1 + p3;
            *reinterpret_cast<float2*>(&Ps[(wk + g) * 72 + col])     = make_float2(p0, p1);
            *reinterpret_cast<float2*>(&Ps[(wk + g + 8) * 72 + col]) = make_float2(p2, p3);
        }
        #pragma unroll
        for (int off = 4; off <= 16; off <<= 1)
            #pragma unroll
            for (int i = 0; i < 4; ++i)
                psum[i] += __shfl_xor_sync(0xffffffffu, psum[i], off);
        if (g == 0) {
            #pragma unroll
            for (int i = 0; i < 4; ++i)
                red[mh * 64 + wq + (i >> 1) * 8 + 2 * t + (i & 1)] = psum[i];
        }
        __syncthreads();                        // Ps + sums visible
        #pragma unroll
        for (int i = 0; i < 4; ++i) {
            int col = wq + (i >> 1) * 8 + 2 * t + (i & 1);
            lC[i] += red[col] + red[64 + col];
        }

        // ---- MMA2: O[c=64][q=64] += V @ P ----
        #pragma unroll
        for (int ks = 0; ks < TK; ks += 8) {
            uint32_t af[2][4], bf[2][2];
            #pragma unroll
            for (int mto = 0; mto < 2; ++mto) {
                int row = wc + mto * 16 + g;
                af[mto][0] = f2tf(Vc[row * 36 + ks + t]);
                af[mto][1] = f2tf(Vc[(row + 8) * 36 + ks + t]);
                af[mto][2] = f2tf(Vc[row * 36 + ks + t + 4]);
                af[mto][3] = f2tf(Vc[(row + 8) * 36 + ks + t + 4]);
            }
            #pragma unroll
            for (int nt = 0; nt < 2; ++nt) {
                int col = wq + nt * 8 + g;
                bf[nt][0] = f2tf(Ps[(ks + t) * 72 + col]);
                bf[nt][1] = f2tf(Ps[(ks + t + 4) * 72 + col]);
            }
            #pragma unroll
            for (int mto = 0; mto < 2; ++mto)
                #pragma unroll
                for (int nt = 0; nt < 2; ++nt)
                    mma_tf32(accO[mto][nt], af[mto], bf[nt]);
        }
    }

    // ---- epilogue: O / l -> AT ----
    float* ATz = AT + (size_t)z * DH * SS;
    #pragma unroll
    for (int mto = 0; mto < 2; ++mto) {
        int rc = wc + mto * 16 + g;
        #pragma unroll
        for (int nt = 0; nt < 2; ++nt) {
            int col = q0 + wq + nt * 8 + 2 * t;
            float i0 = 1.f / lC[nt * 2];
            float i1 = 1.f / lC[nt * 2 + 1];
            float2 r0, r1;
            r0.x = accO[mto][nt][0] * i0;
            r0.y = accO[mto][nt][1] * i1;
            r1.x = accO[mto][nt][2] * i0;
            r1.y = accO[mto][nt][3] * i1;
            *reinterpret_cast<float2*>(&ATz[(size_t)rc * SS + col]) = r0;
            *reinterpret_cast<float2*>(&ATz[(size_t)(rc + 8) * SS + col]) = r1;
        }
    }
}

// ============================================================================
extern "C" void kernel_launch(void* const* d_in, const int* in_sizes, int n_in,
                              void* d_out, int out_size)
{
    (void)in_sizes; (void)n_in; (void)out_size;
    const float* q       = (const float*)d_in[0];
    const float* k       = (const float*)d_in[1];
    const float* v       = (const float*)d_in[2];
    const float* qk_mask = (const float*)d_in[3];
    const float* k_mask  = (const float*)d_in[4];
    const float* Wq = (const float*)d_in[5];
    const float* bq = (const float*)d_in[6];
    const float* Wk = (const float*)d_in[7];
    const float* bk = (const float*)d_in[8];
    const float* Wv = (const float*)d_in[9];
    const float* bv = (const float*)d_in[10];
    const float* Wo = (const float*)d_in[11];
    const float* bo = (const float*)d_in[12];
    float* out = (float*)d_out;

    float *QP, *KP, *VP, *AT;
    cudaGetSymbolAddress((void**)&QP, g_QP);
    cudaGetSymbolAddress((void**)&KP, g_KP);
    cudaGetSymbolAddress((void**)&VP, g_VP);
    cudaGetSymbolAddress((void**)&AT, g_AT);

    // 1) merged Q/K/V projections (one launch, 6 z-slices)
    QKVParams p;
    p.W[0] = Wq;  p.W[1] = Wk;  p.W[2] = Wv;
    p.bias[0] = bq; p.bias[1] = bk; p.bias[2] = bv;
    p.X[0] = q;   p.X[1] = k;   p.X[2] = v;
    p.C[0] = QP;  p.C[1] = KP;  p.C[2] = VP;
    qkv_gemm<<<dim3(SS / 128, DD / 128, 6), 256>>>(p);

    // 2) fused flash attention
    const int FL_SMEM = (64 * 72 + 2 * 64 * 40 + 2 * 64 * 36 + 32 * 72 + 128) * 4;
    cudaFuncSetAttribute(flash_attn, cudaFuncAttributeMaxDynamicSharedMemorySize, FL_SMEM);
    flash_attn<<<dim3(SS / TQ, BB * HH), 256, FL_SMEM>>>(QP, KP, VP, qk_mask, k_mask, AT);

    // 3) output projection
    out_gemm<<<dim3(SS / 128, DD / 128, BB), 256>>>(Wo, AT, bo, out);
}

// round 6
// speedup vs baseline: 4.3120x; 1.0013x over previous
#include <cuda_runtime.h>
#include <stdint.h>
#include <math.h>

#define BB 2
#define EE 1024
#define SS 2048
#define HH 16
#define DD 1024
#define DH 64
#define TQ 64
#define TK 32

// ---- scratch (static __device__ arrays; no allocations allowed) ----
__device__ float g_QP[(size_t)BB * DD * SS];
__device__ float g_KP[(size_t)BB * DD * SS];
__device__ float g_VP[(size_t)BB * DD * SS];
__device__ float g_AT[(size_t)BB * DD * SS];

__device__ __forceinline__ uint32_t f2tf(float x) {
    uint32_t u;
    asm("cvt.rna.tf32.f32 %0, %1;" : "=r"(u) : "f"(x));
    return u;
}

__device__ __forceinline__ void mma_tf32(float* c, const uint32_t* a, const uint32_t* b) {
    asm volatile(
        "mma.sync.aligned.m16n8k8.row.col.f32.tf32.tf32.f32 "
        "{%0,%1,%2,%3}, {%4,%5,%6,%7}, {%8,%9}, {%0,%1,%2,%3};"
        : "+f"(c[0]), "+f"(c[1]), "+f"(c[2]), "+f"(c[3])
        : "r"(a[0]), "r"(a[1]), "r"(a[2]), "r"(a[3]), "r"(b[0]), "r"(b[1]));
}

__device__ __forceinline__ void cp16(void* smem, const void* gmem) {
    uint32_t s = (uint32_t)__cvta_generic_to_shared(smem);
    asm volatile("cp.async.cg.shared.global [%0], [%1], 16;\n" :: "r"(s), "l"(gmem));
}
__device__ __forceinline__ void cp_commit() { asm volatile("cp.async.commit_group;\n"); }
template <int N>
__device__ __forceinline__ void cp_wait() { asm volatile("cp.async.wait_group %0;\n" :: "n"(N)); }

// ============================================================================
// Shared tf32 GEMM core: C[m,n] = sum_k A[m,k]*B[k,n] + bias[m].
// 128x128x16 tiles, 3-stage cp.async pipeline, 8 warps (2x4), 64x32 warp tile.
// ============================================================================
template <int BM, int BN>
__device__ __forceinline__ void gemm_core(
    const float* __restrict__ A, const float* __restrict__ Bmat,
    const float* __restrict__ bias, float* __restrict__ C,
    int K, int lda, int ldb, int ldc, int m0, int n0)
{
    constexpr int BK = 16;
    constexpr int THREADS = 256;
    constexpr int MT = 4, NT = 4;
    constexpr int AST = 20;
    constexpr int BST = BN + 8;
    constexpr int STG = 3;
    constexpr int AV = BM * BK / 4 / THREADS;
    constexpr int BV = BK * BN / 4 / THREADS;

    const int niter = K / BK;

    __shared__ __align__(16) float As[STG][BM * AST];
    __shared__ __align__(16) float Bs[STG][BK * BST];

    const int tid  = threadIdx.x;
    const int lane = tid & 31;
    const int wid  = tid >> 5;
    const int g    = lane >> 2;
    const int t    = lane & 3;
    const int wm   = (wid >> 2) * 64;
    const int wn   = (wid & 3) * 32;

    auto issue = [&](int it, int s) {
        const int k0 = it * BK;
        #pragma unroll
        for (int j = 0; j < AV; ++j) {
            int v = tid + j * THREADS;
            int mr = v / (BK / 4), c4 = (v % (BK / 4)) * 4;
            cp16(&As[s][mr * AST + c4], &A[(size_t)(m0 + mr) * lda + k0 + c4]);
        }
        #pragma unroll
        for (int j = 0; j < BV; ++j) {
            int v = tid + j * THREADS;
            int kr = v / (BN / 4), c4 = (v % (BN / 4)) * 4;
            cp16(&Bs[s][kr * BST + c4], &Bmat[(size_t)(k0 + kr) * ldb + n0 + c4]);
        }
        cp_commit();
    };

    float acc[MT][NT][4] = {};

    issue(0, 0);
    if (niter > 1) issue(1, 1);

    for (int i = 0; i < niter; ++i) {
        const int cur = i % STG;
        if (i + 1 < niter) cp_wait<1>(); else cp_wait<0>();
        __syncthreads();
        if (i + 2 < niter) issue(i + 2, (i + 2) % STG);

        #pragma unroll
        for (int ks = 0; ks < BK; ks += 8) {
            uint32_t af[MT][4], bf[NT][2];
            #pragma unroll
            for (int mt = 0; mt < MT; ++mt) {
                int row = wm + mt * 16 + g;
                af[mt][0] = f2tf(As[cur][row * AST + ks + t]);
                af[mt][1] = f2tf(As[cur][(row + 8) * AST + ks + t]);
                af[mt][2] = f2tf(As[cur][row * AST + ks + t + 4]);
                af[mt][3] = f2tf(As[cur][(row + 8) * AST + ks + t + 4]);
            }
            #pragma unroll
            for (int nt = 0; nt < NT; ++nt) {
                int col = wn + nt * 8 + g;
                bf[nt][0] = f2tf(Bs[cur][(ks + t) * BST + col]);
                bf[nt][1] = f2tf(Bs[cur][(ks + t + 4) * BST + col]);
            }
            #pragma unroll
            for (int mt = 0; mt < MT; ++mt)
                #pragma unroll
                for (int nt = 0; nt < NT; ++nt)
                    mma_tf32(acc[mt][nt], af[mt], bf[nt]);
        }
        __syncthreads();
    }

    #pragma unroll
    for (int mt = 0; mt < MT; ++mt) {
        int mg = m0 + wm + mt * 16 + g;
        float b0 = bias ? bias[mg] : 0.f;
        float b1 = bias ? bias[mg + 8] : 0.f;
        #pragma unroll
        for (int nt = 0; nt < NT; ++nt) {
            int n = n0 + wn + nt * 8 + 2 * t;
            float2 r0, r1;
            r0.x = acc[mt][nt][0] + b0;
            r0.y = acc[mt][nt][1] + b0;
            r1.x = acc[mt][nt][2] + b1;
            r1.y = acc[mt][nt][3] + b1;
            *reinterpret_cast<float2*>(&C[(size_t)mg * ldc + n]) = r0;
            *reinterpret_cast<float2*>(&C[(size_t)(mg + 8) * ldc + n]) = r1;
        }
    }
}

struct QKVParams {
    const float* W[3];
    const float* bias[3];
    const float* X[3];
    float* C[3];
};

// merged Q/K/V projections: z = mat*2 + batch
__global__ void __launch_bounds__(256, 2)
qkv_gemm(QKVParams p)
{
    const int mat = blockIdx.z >> 1;
    const int b   = blockIdx.z & 1;
    gemm_core<128, 128>(p.W[mat], p.X[mat] + (size_t)b * EE * SS, p.bias[mat],
                        p.C[mat] + (size_t)b * DD * SS,
                        EE, EE, SS, SS, blockIdx.y * 128, blockIdx.x * 128);
}

// output projection
__global__ void __launch_bounds__(256, 2)
out_gemm(const float* __restrict__ Wo, const float* __restrict__ AT,
         const float* __restrict__ bo, float* __restrict__ out)
{
    const int b = blockIdx.z;
    gemm_core<128, 128>(Wo, AT + (size_t)b * DD * SS, bo,
                        out + (size_t)b * DD * SS,
                        DD, DD, SS, SS, blockIdx.y * 128, blockIdx.x * 128);
}

// ============================================================================
// Fused flash attention. Block = (b*H+h, q-tile of 64). 256 threads, 8 warps.
// Double-buffered K/V (TK=32) via cp.async: tile kt+1 issued right after the
// top-of-iteration sync, overlapping all of compute(kt).
// qk_mask read only on diagonal tiles (k0+TK > q0); k_mask always added.
// Conflict-free smem strides: Qs/Ps 72, Ks 40, Vs 36.
// ============================================================================
__global__ void __launch_bounds__(256, 2)
flash_attn(const float* __restrict__ QP, const float* __restrict__ KP,
           const float* __restrict__ VP, const float* __restrict__ qk_mask,
           const float* __restrict__ k_mask, float* __restrict__ AT)
{
    extern __shared__ __align__(16) float smf[];
    float* Qs = smf;                       // [64 c][64 q] st 72
    float* Ks = Qs + 64 * 72;              // 2 x [64 c][32 k] st 40
    float* Vs = Ks + 2 * 64 * 40;          // 2 x [64 c][32 k] st 36
    float* Ps = Vs + 2 * 64 * 36;          // [32 k][64 q] st 72
    float* red = Ps + 32 * 72;             // [2][64]

    const int z   = blockIdx.y;
    const int b   = z / HH;
    const int q0  = blockIdx.x * TQ;
    const int tid  = threadIdx.x;
    const int lane = tid & 31;
    const int wid  = tid >> 5;
    const int g  = lane >> 2;
    const int t  = lane & 3;
    const int mh = wid >> 2;               // 0/1
    const int wq = (wid & 3) * 16;
    const int wk = mh * 16;                // MMA1 k-half
    const int wc = mh * 32;                // MMA2 c-half

    const float* Qg = QP + (size_t)z * DH * SS;
    const float* Kg = KP + (size_t)z * DH * SS;
    const float* Vg = VP + (size_t)z * DH * SS;
    const float* qm = qk_mask + (size_t)b * SS * SS;
    const float* km = k_mask + (size_t)b * SS;

    // Q tile: 64 rows x 64 cols
    #pragma unroll
    for (int j = 0; j < 4; ++j) {
        int v = tid + j * 256;
        int r = v >> 4, c4 = (v & 15) << 2;
        cp16(&Qs[r * 72 + c4], &Qg[(size_t)r * SS + q0 + c4]);
    }
    cp_commit();

    auto issue = [&](int kt, int s) {
        const int k0 = kt * TK;
        #pragma unroll
        for (int j = 0; j < 2; ++j) {
            int v = tid + j * 256;
            int r = v >> 3, c4 = (v & 7) << 2;
            cp16(&Ks[s * 64 * 40 + r * 40 + c4], &Kg[(size_t)r * SS + k0 + c4]);
            cp16(&Vs[s * 64 * 36 + r * 36 + c4], &Vg[(size_t)r * SS + k0 + c4]);
        }
        cp_commit();
    };

    float accO[2][2][4] = {};
    float mC[4], lC[4];
    #pragma unroll
    for (int i = 0; i < 4; ++i) { mC[i] = -1e30f; lC[i] = 0.f; }

    const int nkt = q0 / TK + 2;
    issue(0, 0);

    for (int kt = 0; kt < nkt; ++kt) {
        const int cur = kt & 1;
        const int k0  = kt * TK;
        const float* Kc = Ks + cur * 64 * 40;
        const float* Vc = Vs + cur * 64 * 36;

        cp_wait<0>();
        __syncthreads();                        // tile kt ready; iter kt-1 fully done
        if (kt + 1 < nkt) issue(kt + 1, cur ^ 1);

        // ---- MMA1: S[k=32][q=64] = K^T Q ----
        float acc[2][4] = {};
        #pragma unroll
        for (int ks = 0; ks < DH; ks += 8) {
            uint32_t af[4], bf[2][2];
            af[0] = f2tf(Kc[(ks + t) * 40 + wk + g]);
            af[1] = f2tf(Kc[(ks + t) * 40 + wk + g + 8]);
            af[2] = f2tf(Kc[(ks + t + 4) * 40 + wk + g]);
            af[3] = f2tf(Kc[(ks + t + 4) * 40 + wk + g + 8]);
            #pragma unroll
            for (int nt = 0; nt < 2; ++nt) {
                int col = wq + nt * 8 + g;
                bf[nt][0] = f2tf(Qs[(ks + t) * 72 + col]);
                bf[nt][1] = f2tf(Qs[(ks + t + 4) * 72 + col]);
            }
            mma_tf32(acc[0], af, bf[0]);
            mma_tf32(acc[1], af, bf[1]);
        }

        // ---- scale + masks; tile max ----
        const int rk0 = k0 + wk + g;
        const float km0 = __ldg(&km[rk0]);
        const float km1 = __ldg(&km[rk0 + 8]);
        float pmax[4];
        const bool diag = (k0 + TK > q0);
        #pragma unroll
        for (int nt = 0; nt < 2; ++nt) {
            int cq = q0 + wq + nt * 8 + 2 * t;
            float a0 = km0, a1 = km0, a2 = km1, a3 = km1;
            if (diag) {
                float2 m0 = *reinterpret_cast<const float2*>(&qm[(size_t)rk0 * SS + cq]);
                float2 m1 = *reinterpret_cast<const float2*>(&qm[(size_t)(rk0 + 8) * SS + cq]);
                a0 += m0.x; a1 += m0.y; a2 += m1.x; a3 += m1.y;
            }
            acc[nt][0] = fmaf(acc[nt][0], 0.125f, a0);
            acc[nt][1] = fmaf(acc[nt][1], 0.125f, a1);
            acc[nt][2] = fmaf(acc[nt][2], 0.125f, a2);
            acc[nt][3] = fmaf(acc[nt][3], 0.125f, a3);
            pmax[nt * 2]     = fmaxf(acc[nt][0], acc[nt][2]);
            pmax[nt * 2 + 1] = fmaxf(acc[nt][1], acc[nt][3]);
        }
        #pragma unroll
        for (int off = 4; off <= 16; off <<= 1)
            #pragma unroll
            for (int i = 0; i < 4; ++i)
                pmax[i] = fmaxf(pmax[i], __shfl_xor_sync(0xffffffffu, pmax[i], off));
        if (g == 0) {
            #pragma unroll
            for (int i = 0; i < 4; ++i)
                red[mh * 64 + wq + (i >> 1) * 8 + 2 * t + (i & 1)] = pmax[i];
        }
        __syncthreads();

        float fac[4];
        #pragma unroll
        for (int i = 0; i < 4; ++i) {
            int col = wq + (i >> 1) * 8 + 2 * t + (i & 1);
            float tm = fmaxf(red[col], red[64 + col]);
            float mn = fmaxf(mC[i], tm);
            fac[i] = __expf(mC[i] - mn);
            mC[i] = mn;
            lC[i] *= fac[i];
        }
        #pragma unroll
        for (int mto = 0; mto < 2; ++mto)
            #pragma unroll
            for (int nt = 0; nt < 2; ++nt) {
                accO[mto][nt][0] *= fac[nt * 2];
                accO[mto][nt][1] *= fac[nt * 2 + 1];
                accO[mto][nt][2] *= fac[nt * 2];
                accO[mto][nt][3] *= fac[nt * 2 + 1];
            }

        // ---- P = exp(S - m) -> Ps; partial sums ----
        float psum[4];
        #pragma unroll
        for (int nt = 0; nt < 2; ++nt) {
            int col = wq + nt * 8 + 2 * t;
            float p0 = __expf(acc[nt][0] - mC[nt * 2]);
            float p1 = __expf(acc[nt][1] - mC[nt * 2 + 1]);
            float p2 = __expf(acc[nt][2] - mC[nt * 2]);
            float p3 = __expf(acc[nt][3] - mC[nt * 2 + 1]);
            psum[nt * 2]     = p0 + p2;
            psum[nt * 2 + 1] = p1 + p3;
            *reinterpret_cast<float2*>(&Ps[(wk + g) * 72 + col])     = make_float2(p0, p1);
            *reinterpret_cast<float2*>(&Ps[(wk + g + 8) * 72 + col]) = make_float2(p2, p3);
        }
        #pragma unroll
        for (int off = 4; off <= 16; off <<= 1)
            #pragma unroll
            for (int i = 0; i < 4; ++i)
                psum[i] += __shfl_xor_sync(0xffffffffu, psum[i], off);
        if (g == 0) {
            #pragma unroll
            for (int i = 0; i < 4; ++i)
                red[mh * 64 + wq + (i >> 1) * 8 + 2 * t + (i & 1)] = psum[i];
        }
        __syncthreads();                        // Ps + sums visible
        #pragma unroll
        for (int i = 0; i < 4; ++i) {
            int col = wq + (i >> 1) * 8 + 2 * t + (i & 1);
            lC[i] += red[col] + red[64 + col];
        }

        // ---- MMA2: O[c=64][q=64] += V @ P ----
        #pragma unroll
        for (int ks = 0; ks < TK; ks += 8) {
            uint32_t af[2][4], bf[2][2];
            #pragma unroll
            for (int mto = 0; mto < 2; ++mto) {
                int row = wc + mto * 16 + g;
                af[mto][0] = f2tf(Vc[row * 36 + ks + t]);
                af[mto][1] = f2tf(Vc[(row + 8) * 36 + ks + t]);
                af[mto][2] = f2tf(Vc[row * 36 + ks + t + 4]);
                af[mto][3] = f2tf(Vc[(row + 8) * 36 + ks + t + 4]);
            }
            #pragma unroll
            for (int nt = 0; nt < 2; ++nt) {
                int col = wq + nt * 8 + g;
                bf[nt][0] = f2tf(Ps[(ks + t) * 72 + col]);
                bf[nt][1] = f2tf(Ps[(ks + t + 4) * 72 + col]);
            }
            #pragma unroll
            for (int mto = 0; mto < 2; ++mto)
                #pragma unroll
                for (int nt = 0; nt < 2; ++nt)
                    mma_tf32(accO[mto][nt], af[mto], bf[nt]);
        }
    }

    // ---- epilogue: O / l -> AT ----
    float* ATz = AT + (size_t)z * DH * SS;
    #pragma unroll
    for (int mto = 0; mto < 2; ++mto) {
        int rc = wc + mto * 16 + g;
        #pragma unroll
        for (int nt = 0; nt < 2; ++nt) {
            int col = q0 + wq + nt * 8 + 2 * t;
            float i0 = 1.f / lC[nt * 2];
            float i1 = 1.f / lC[nt * 2 + 1];
            float2 r0, r1;
            r0.x = accO[mto][nt][0] * i0;
            r0.y = accO[mto][nt][1] * i1;
            r1.x = accO[mto][nt][2] * i0;
            r1.y = accO[mto][nt][3] * i1;
            *reinterpret_cast<float2*>(&ATz[(size_t)rc * SS + col]) = r0;
            *reinterpret_cast<float2*>(&ATz[(size_t)(rc + 8) * SS + col]) = r1;
        }
    }
}

// ============================================================================
extern "C" void kernel_launch(void* const* d_in, const int* in_sizes, int n_in,
                              void* d_out, int out_size)
{
    (void)in_sizes; (void)n_in; (void)out_size;
    const float* q       = (const float*)d_in[0];
    const float* k       = (const float*)d_in[1];
    const float* v       = (const float*)d_in[2];
    const float* qk_mask = (const float*)d_in[3];
    const float* k_mask  = (const float*)d_in[4];
    const float* Wq = (const float*)d_in[5];
    const float* bq = (const float*)d_in[6];
    const float* Wk = (const float*)d_in[7];
    const float* bk = (const float*)d_in[8];
    const float* Wv = (const float*)d_in[9];
    const float* bv = (const float*)d_in[10];
    const float* Wo = (const float*)d_in[11];
    const float* bo = (const float*)d_in[12];
    float* out = (float*)d_out;

    float *QP, *KP, *VP, *AT;
    cudaGetSymbolAddress((void**)&QP, g_QP);
    cudaGetSymbolAddress((void**)&KP, g_KP);
    cudaGetSymbolAddress((void**)&VP, g_VP);
    cudaGetSymbolAddress((void**)&AT, g_AT);

    // 1) merged Q/K/V projections (one launch, 6 z-slices)
    QKVParams p;
    p.W[0] = Wq;  p.W[1] = Wk;  p.W[2] = Wv;
    p.bias[0] = bq; p.bias[1] = bk; p.bias[2] = bv;
    p.X[0] = q;   p.X[1] = k;   p.X[2] = v;
    p.C[0] = QP;  p.C[1] = KP;  p.C[2] = VP;
    qkv_gemm<<<dim3(SS / 128, DD / 128, 6), 256>>>(p);

    // 2) fused flash attention
    const int FL_SMEM = (64 * 72 + 2 * 64 * 40 + 2 * 64 * 36 + 32 * 72 + 128) * 4;
    cudaFuncSetAttribute(flash_attn, cudaFuncAttributeMaxDynamicSharedMemorySize, FL_SMEM);
    flash_attn<<<dim3(SS / TQ, BB * HH), 256, FL_SMEM>>>(QP, KP, VP, qk_mask, k_mask, AT);

    // 3) output projection
    out_gemm<<<dim3(SS / 128, DD / 128, BB), 256>>>(Wo, AT, bo, out);
}

// round 7
// speedup vs baseline: 4.3329x; 1.0048x over previous
#include <cuda_runtime.h>
#include <stdint.h>
#include <math.h>

#define BB 2
#define EE 1024
#define SS 2048
#define HH 16
#define DD 1024
#define DH 64
#define TQ 64
#define TK 32

// ---- scratch (static __device__ arrays; no allocations allowed) ----
__device__ float g_QP[(size_t)BB * DD * SS];
__device__ float g_KP[(size_t)BB * DD * SS];
__device__ float g_VP[(size_t)BB * DD * SS];
__device__ float g_AT[(size_t)BB * DD * SS];

__device__ __forceinline__ uint32_t f2tf(float x) {
    uint32_t u;
    asm("cvt.rna.tf32.f32 %0, %1;" : "=r"(u) : "f"(x));
    return u;
}

__device__ __forceinline__ void mma_tf32(float* c, const uint32_t* a, const uint32_t* b) {
    asm volatile(
        "mma.sync.aligned.m16n8k8.row.col.f32.tf32.tf32.f32 "
        "{%0,%1,%2,%3}, {%4,%5,%6,%7}, {%8,%9}, {%0,%1,%2,%3};"
        : "+f"(c[0]), "+f"(c[1]), "+f"(c[2]), "+f"(c[3])
        : "r"(a[0]), "r"(a[1]), "r"(a[2]), "r"(a[3]), "r"(b[0]), "r"(b[1]));
}

__device__ __forceinline__ void cp16(void* smem, const void* gmem) {
    uint32_t s = (uint32_t)__cvta_generic_to_shared(smem);
    asm volatile("cp.async.cg.shared.global [%0], [%1], 16;\n" :: "r"(s), "l"(gmem));
}
__device__ __forceinline__ void cp_commit() { asm volatile("cp.async.commit_group;\n"); }
template <int N>
__device__ __forceinline__ void cp_wait() { asm volatile("cp.async.wait_group %0;\n" :: "n"(N)); }

// ============================================================================
// Shared tf32 GEMM core: C[m,n] = sum_k A[m,k]*B[k,n] + bias[m].
// 128x128x16 tiles, 3-stage cp.async pipeline, 8 warps (2x4), 64x32 warp tile.
// ============================================================================
template <int BM, int BN>
__device__ __forceinline__ void gemm_core(
    const float* __restrict__ A, const float* __restrict__ Bmat,
    const float* __restrict__ bias, float* __restrict__ C,
    int K, int lda, int ldb, int ldc, int m0, int n0)
{
    constexpr int BK = 16;
    constexpr int THREADS = 256;
    constexpr int MT = 4, NT = 4;
    constexpr int AST = 20;
    constexpr int BST = BN + 8;
    constexpr int STG = 3;
    constexpr int AV = BM * BK / 4 / THREADS;
    constexpr int BV = BK * BN / 4 / THREADS;

    const int niter = K / BK;

    __shared__ __align__(16) float As[STG][BM * AST];
    __shared__ __align__(16) float Bs[STG][BK * BST];

    const int tid  = threadIdx.x;
    const int lane = tid & 31;
    const int wid  = tid >> 5;
    const int g    = lane >> 2;
    const int t    = lane & 3;
    const int wm   = (wid >> 2) * 64;
    const int wn   = (wid & 3) * 32;

    auto issue = [&](int it, int s) {
        const int k0 = it * BK;
        #pragma unroll
        for (int j = 0; j < AV; ++j) {
            int v = tid + j * THREADS;
            int mr = v / (BK / 4), c4 = (v % (BK / 4)) * 4;
            cp16(&As[s][mr * AST + c4], &A[(size_t)(m0 + mr) * lda + k0 + c4]);
        }
        #pragma unroll
        for (int j = 0; j < BV; ++j) {
            int v = tid + j * THREADS;
            int kr = v / (BN / 4), c4 = (v % (BN / 4)) * 4;
            cp16(&Bs[s][kr * BST + c4], &Bmat[(size_t)(k0 + kr) * ldb + n0 + c4]);
        }
        cp_commit();
    };

    float acc[MT][NT][4] = {};

    issue(0, 0);
    if (niter > 1) issue(1, 1);

    for (int i = 0; i < niter; ++i) {
        const int cur = i % STG;
        if (i + 1 < niter) cp_wait<1>(); else cp_wait<0>();
        __syncthreads();
        if (i + 2 < niter) issue(i + 2, (i + 2) % STG);

        #pragma unroll
        for (int ks = 0; ks < BK; ks += 8) {
            uint32_t af[MT][4], bf[NT][2];
            #pragma unroll
            for (int mt = 0; mt < MT; ++mt) {
                int row = wm + mt * 16 + g;
                af[mt][0] = f2tf(As[cur][row * AST + ks + t]);
                af[mt][1] = f2tf(As[cur][(row + 8) * AST + ks + t]);
                af[mt][2] = f2tf(As[cur][row * AST + ks + t + 4]);
                af[mt][3] = f2tf(As[cur][(row + 8) * AST + ks + t + 4]);
            }
            #pragma unroll
            for (int nt = 0; nt < NT; ++nt) {
                int col = wn + nt * 8 + g;
                bf[nt][0] = f2tf(Bs[cur][(ks + t) * BST + col]);
                bf[nt][1] = f2tf(Bs[cur][(ks + t + 4) * BST + col]);
            }
            #pragma unroll
            for (int mt = 0; mt < MT; ++mt)
                #pragma unroll
                for (int nt = 0; nt < NT; ++nt)
                    mma_tf32(acc[mt][nt], af[mt], bf[nt]);
        }
        __syncthreads();
    }

    #pragma unroll
    for (int mt = 0; mt < MT; ++mt) {
        int mg = m0 + wm + mt * 16 + g;
        float b0 = bias ? bias[mg] : 0.f;
        float b1 = bias ? bias[mg + 8] : 0.f;
        #pragma unroll
        for (int nt = 0; nt < NT; ++nt) {
            int n = n0 + wn + nt * 8 + 2 * t;
            float2 r0, r1;
            r0.x = acc[mt][nt][0] + b0;
            r0.y = acc[mt][nt][1] + b0;
            r1.x = acc[mt][nt][2] + b1;
            r1.y = acc[mt][nt][3] + b1;
            *reinterpret_cast<float2*>(&C[(size_t)mg * ldc + n]) = r0;
            *reinterpret_cast<float2*>(&C[(size_t)(mg + 8) * ldc + n]) = r1;
        }
    }
}

struct QKVParams {
    const float* W[3];
    const float* bias[3];
    const float* X[3];
    float* C[3];
};

// merged Q/K/V projections: z = mat*2 + batch
__global__ void __launch_bounds__(256, 2)
qkv_gemm(QKVParams p)
{
    const int mat = blockIdx.z >> 1;
    const int b   = blockIdx.z & 1;
    gemm_core<128, 128>(p.W[mat], p.X[mat] + (size_t)b * EE * SS, p.bias[mat],
                        p.C[mat] + (size_t)b * DD * SS,
                        EE, EE, SS, SS, blockIdx.y * 128, blockIdx.x * 128);
}

// output projection
__global__ void __launch_bounds__(256, 2)
out_gemm(const float* __restrict__ Wo, const float* __restrict__ AT,
         const float* __restrict__ bo, float* __restrict__ out)
{
    const int b = blockIdx.z;
    gemm_core<128, 128>(Wo, AT + (size_t)b * DD * SS, bo,
                        out + (size_t)b * DD * SS,
                        DD, DD, SS, SS, blockIdx.y * 128, blockIdx.x * 128);
}

// ============================================================================
// Fused flash attention. Block = (b*H+h, q-tile of 64). 256 threads, 8 warps.
// Double-buffered K/V (TK=32) via cp.async: tile kt+1 issued right after the
// top-of-iteration sync, overlapping all of compute(kt).
// qk_mask read only on diagonal tiles (k0+TK > q0); k_mask always added.
// Conflict-free smem strides: Qs/Ps 72, Ks 40, Vs 36.
// ============================================================================
__global__ void __launch_bounds__(256, 2)
flash_attn(const float* __restrict__ QP, const float* __restrict__ KP,
           const float* __restrict__ VP, const float* __restrict__ qk_mask,
           const float* __restrict__ k_mask, float* __restrict__ AT)
{
    extern __shared__ __align__(16) float smf[];
    float* Qs = smf;                       // [64 c][64 q] st 72
    float* Ks = Qs + 64 * 72;              // 2 x [64 c][32 k] st 40
    float* Vs = Ks + 2 * 64 * 40;          // 2 x [64 c][32 k] st 36
    float* Ps = Vs + 2 * 64 * 36;          // [32 k][64 q] st 72
    float* red = Ps + 32 * 72;             // [2][64]

    const int z   = blockIdx.y;
    const int b   = z / HH;
    const int q0  = blockIdx.x * TQ;
    const int tid  = threadIdx.x;
    const int lane = tid & 31;
    const int wid  = tid >> 5;
    const int g  = lane >> 2;
    const int t  = lane & 3;
    const int mh = wid >> 2;               // 0/1
    const int wq = (wid & 3) * 16;
    const int wk = mh * 16;                // MMA1 k-half
    const int wc = mh * 32;                // MMA2 c-half

    const float* Qg = QP + (size_t)z * DH * SS;
    const float* Kg = KP + (size_t)z * DH * SS;
    const float* Vg = VP + (size_t)z * DH * SS;
    const float* qm = qk_mask + (size_t)b * SS * SS;
    const float* km = k_mask + (size_t)b * SS;

    // Q tile: 64 rows x 64 cols
    #pragma unroll
    for (int j = 0; j < 4; ++j) {
        int v = tid + j * 256;
        int r = v >> 4, c4 = (v & 15) << 2;
        cp16(&Qs[r * 72 + c4], &Qg[(size_t)r * SS + q0 + c4]);
    }
    cp_commit();

    auto issue = [&](int kt, int s) {
        const int k0 = kt * TK;
        #pragma unroll
        for (int j = 0; j < 2; ++j) {
            int v = tid + j * 256;
            int r = v >> 3, c4 = (v & 7) << 2;
            cp16(&Ks[s * 64 * 40 + r * 40 + c4], &Kg[(size_t)r * SS + k0 + c4]);
            cp16(&Vs[s * 64 * 36 + r * 36 + c4], &Vg[(size_t)r * SS + k0 + c4]);
        }
        cp_commit();
    };

    float accO[2][2][4] = {};
    float mC[4], lC[4];
    #pragma unroll
    for (int i = 0; i < 4; ++i) { mC[i] = -1e30f; lC[i] = 0.f; }

    const int nkt = q0 / TK + 2;
    issue(0, 0);

    for (int kt = 0; kt < nkt; ++kt) {
        const int cur = kt & 1;
        const int k0  = kt * TK;
        const float* Kc = Ks + cur * 64 * 40;
        const float* Vc = Vs + cur * 64 * 36;

        cp_wait<0>();
        __syncthreads();                        // tile kt ready; iter kt-1 fully done
        if (kt + 1 < nkt) issue(kt + 1, cur ^ 1);

        // ---- MMA1: S[k=32][q=64] = K^T Q ----
        float acc[2][4] = {};
        #pragma unroll
        for (int ks = 0; ks < DH; ks += 8) {
            uint32_t af[4], bf[2][2];
            af[0] = f2tf(Kc[(ks + t) * 40 + wk + g]);
            af[1] = f2tf(Kc[(ks + t) * 40 + wk + g + 8]);
            af[2] = f2tf(Kc[(ks + t + 4) * 40 + wk + g]);
            af[3] = f2tf(Kc[(ks + t + 4) * 40 + wk + g + 8]);
            #pragma unroll
            for (int nt = 0; nt < 2; ++nt) {
                int col = wq + nt * 8 + g;
                bf[nt][0] = f2tf(Qs[(ks + t) * 72 + col]);
                bf[nt][1] = f2tf(Qs[(ks + t + 4) * 72 + col]);
            }
            mma_tf32(acc[0], af, bf[0]);
            mma_tf32(acc[1], af, bf[1]);
        }

        // ---- scale + masks; tile max ----
        const int rk0 = k0 + wk + g;
        const float km0 = __ldg(&km[rk0]);
        const float km1 = __ldg(&km[rk0 + 8]);
        float pmax[4];
        const bool diag = (k0 + TK > q0);
        #pragma unroll
        for (int nt = 0; nt < 2; ++nt) {
            int cq = q0 + wq + nt * 8 + 2 * t;
            float a0 = km0, a1 = km0, a2 = km1, a3 = km1;
            if (diag) {
                float2 m0 = *reinterpret_cast<const float2*>(&qm[(size_t)rk0 * SS + cq]);
                float2 m1 = *reinterpret_cast<const float2*>(&qm[(size_t)(rk0 + 8) * SS + cq]);
                a0 += m0.x; a1 += m0.y; a2 += m1.x; a3 += m1.y;
            }
            acc[nt][0] = fmaf(acc[nt][0], 0.125f, a0);
            acc[nt][1] = fmaf(acc[nt][1], 0.125f, a1);
            acc[nt][2] = fmaf(acc[nt][2], 0.125f, a2);
            acc[nt][3] = fmaf(acc[nt][3], 0.125f, a3);
            pmax[nt * 2]     = fmaxf(acc[nt][0], acc[nt][2]);
            pmax[nt * 2 + 1] = fmaxf(acc[nt][1], acc[nt][3]);
        }
        #pragma unroll
        for (int off = 4; off <= 16; off <<= 1)
            #pragma unroll
            for (int i = 0; i < 4; ++i)
                pmax[i] = fmaxf(pmax[i], __shfl_xor_sync(0xffffffffu, pmax[i], off));
        if (g == 0) {
            #pragma unroll
            for (int i = 0; i < 4; ++i)
                red[mh * 64 + wq + (i >> 1) * 8 + 2 * t + (i & 1)] = pmax[i];
        }
        __syncthreads();

        float fac[4];
        #pragma unroll
        for (int i = 0; i < 4; ++i) {
            int col = wq + (i >> 1) * 8 + 2 * t + (i & 1);
            float tm = fmaxf(red[col], red[64 + col]);
            float mn = fmaxf(mC[i], tm);
            fac[i] = __expf(mC[i] - mn);
            mC[i] = mn;
            lC[i] *= fac[i];
        }
        #pragma unroll
        for (int mto = 0; mto < 2; ++mto)
            #pragma unroll
            for (int nt = 0; nt < 2; ++nt) {
                accO[mto][nt][0] *= fac[nt * 2];
                accO[mto][nt][1] *= fac[nt * 2 + 1];
                accO[mto][nt][2] *= fac[nt * 2];
                accO[mto][nt][3] *= fac[nt * 2 + 1];
            }

        // ---- P = exp(S - m) -> Ps; partial sums ----
        float psum[4];
        #pragma unroll
        for (int nt = 0; nt < 2; ++nt) {
            int col = wq + nt * 8 + 2 * t;
            float p0 = __expf(acc[nt][0] - mC[nt * 2]);
            float p1 = __expf(acc[nt][1] - mC[nt * 2 + 1]);
            float p2 = __expf(acc[nt][2] - mC[nt * 2]);
            float p3 = __expf(acc[nt][3] - mC[nt * 2 + 1]);
            psum[nt * 2]     = p0 + p2;
            psum[nt * 2 + 1] = p1 + p3;
            *reinterpret_cast<float2*>(&Ps[(wk + g) * 72 + col])     = make_float2(p0, p1);
            *reinterpret_cast<float2*>(&Ps[(wk + g + 8) * 72 + col]) = make_float2(p2, p3);
        }
        #pragma unroll
        for (int off = 4; off <= 16; off <<= 1)
            #pragma unroll
            for (int i = 0; i < 4; ++i)
                psum[i] += __shfl_xor_sync(0xffffffffu, psum[i], off);
        if (g == 0) {
            #pragma unroll
            for (int i = 0; i < 4; ++i)
                red[mh * 64 + wq + (i >> 1) * 8 + 2 * t + (i & 1)] = psum[i];
        }
        __syncthreads();                        // Ps + sums visible
        #pragma unroll
        for (int i = 0; i < 4; ++i) {
            int col = wq + (i >> 1) * 8 + 2 * t + (i & 1);
            lC[i] += red[col] + red[64 + col];
        }

        // ---- MMA2: O[c=64][q=64] += V @ P ----
        #pragma unroll
        for (int ks = 0; ks < TK; ks += 8) {
            uint32_t af[2][4], bf[2][2];
            #pragma unroll
            for (int mto = 0; mto < 2; ++mto) {
                int row = wc + mto * 16 + g;
                af[mto][0] = f2tf(Vc[row * 36 + ks + t]);
                af[mto][1] = f2tf(Vc[(row + 8) * 36 + ks + t]);
                af[mto][2] = f2tf(Vc[row * 36 + ks + t + 4]);
                af[mto][3] = f2tf(Vc[(row + 8) * 36 + ks + t + 4]);
            }
            #pragma unroll
            for (int nt = 0; nt < 2; ++nt) {
                int col = wq + nt * 8 + g;
                bf[nt][0] = f2tf(Ps[(ks + t) * 72 + col]);
                bf[nt][1] = f2tf(Ps[(ks + t + 4) * 72 + col]);
            }
            #pragma unroll
            for (int mto = 0; mto < 2; ++mto)
                #pragma unroll
                for (int nt = 0; nt < 2; ++nt)
                    mma_tf32(accO[mto][nt], af[mto], bf[nt]);
        }
    }

    // ---- epilogue: O / l -> AT ----
    float* ATz = AT + (size_t)z * DH * SS;
    #pragma unroll
    for (int mto = 0; mto < 2; ++mto) {
        int rc = wc + mto * 16 + g;
        #pragma unroll
        for (int nt = 0; nt < 2; ++nt) {
            int col = q0 + wq + nt * 8 + 2 * t;
            float i0 = 1.f / lC[nt * 2];
            float i1 = 1.f / lC[nt * 2 + 1];
            float2 r0, r1;
            r0.x = accO[mto][nt][0] * i0;
            r0.y = accO[mto][nt][1] * i1;
            r1.x = accO[mto][nt][2] * i0;
            r1.y = accO[mto][nt][3] * i1;
            *reinterpret_cast<float2*>(&ATz[(size_t)rc * SS + col]) = r0;
            *reinterpret_cast<float2*>(&ATz[(size_t)(rc + 8) * SS + col]) = r1;
        }
    }
}

// ============================================================================
extern "C" void kernel_launch(void* const* d_in, const int* in_sizes, int n_in,
                              void* d_out, int out_size)
{
    (void)in_sizes; (void)n_in; (void)out_size;
    const float* q       = (const float*)d_in[0];
    const float* k       = (const float*)d_in[1];
    const float* v       = (const float*)d_in[2];
    const float* qk_mask = (const float*)d_in[3];
    const float* k_mask  = (const float*)d_in[4];
    const float* Wq = (const float*)d_in[5];
    const float* bq = (const float*)d_in[6];
    const float* Wk = (const float*)d_in[7];
    const float* bk = (const float*)d_in[8];
    const float* Wv = (const float*)d_in[9];
    const float* bv = (const float*)d_in[10];
    const float* Wo = (const float*)d_in[11];
    const float* bo = (const float*)d_in[12];
    float* out = (float*)d_out;

    float *QP, *KP, *VP, *AT;
    cudaGetSymbolAddress((void**)&QP, g_QP);
    cudaGetSymbolAddress((void**)&KP, g_KP);
    cudaGetSymbolAddress((void**)&VP, g_VP);
    cudaGetSymbolAddress((void**)&AT, g_AT);

    // 1) merged Q/K/V projections (one launch, 6 z-slices)
    QKVParams p;
    p.W[0] = Wq;  p.W[1] = Wk;  p.W[2] = Wv;
    p.bias[0] = bq; p.bias[1] = bk; p.bias[2] = bv;
    p.X[0] = q;   p.X[1] = k;   p.X[2] = v;
    p.C[0] = QP;  p.C[1] = KP;  p.C[2] = VP;
    qkv_gemm<<<dim3(SS / 128, DD / 128, 6), 256>>>(p);

    // 2) fused flash attention
    const int FL_SMEM = (64 * 72 + 2 * 64 * 40 + 2 * 64 * 36 + 32 * 72 + 128) * 4;
    cudaFuncSetAttribute(flash_attn, cudaFuncAttributeMaxDynamicSharedMemorySize, FL_SMEM);
    flash_attn<<<dim3(SS / TQ, BB * HH), 256, FL_SMEM>>>(QP, KP, VP, qk_mask, k_mask, AT);

    // 3) output projection
    out_gemm<<<dim3(SS / 128, DD / 128, BB), 256>>>(Wo, AT, bo, out);
}